// round 9
// baseline (speedup 1.0000x reference)
#include <cuda_runtime.h>

#define NB   4
#define LEN1 32777
#define M1   4097
#define M2   512
#define CH   256

typedef unsigned long long u64;

// ------- static scratch -------
__device__ float g_out1[NB * M1 * CH];
__device__ float g_gt2[NB * M2 * CH];
__device__ float g_gt1_0[NB * CH];
__device__ float g_attn[NB * M1 * 32];     // softmax attn, (b, m, n*4+h)
__device__ float g_rowdot[NB * LEN1 * 4];  // per-row dot with w_att
__device__ float g_sc1[NB];
__device__ float g_sc2[NB * M2];

// ---- f32x2 helpers ----
__device__ __forceinline__ u64 pk2(float v) {
    u64 r; unsigned int u = __float_as_uint(v);
    asm("mov.b64 %0, {%1, %1};" : "=l"(r) : "r"(u));
    return r;
}
__device__ __forceinline__ void unpk2(u64 v, float& lo, float& hi) {
    unsigned int a, b;
    asm("mov.b64 {%0, %1}, %2;" : "=r"(a), "=r"(b) : "l"(v));
    lo = __uint_as_float(a); hi = __uint_as_float(b);
}
#define FMA2(d, a, b) asm("fma.rn.f32x2 %0, %1, %2, %0;" : "+l"(d) : "l"(a), "l"(b))

// --------------------------------------------------------- finalize
__global__ void finalize_kernel(float* score1, float* score2) {
    int i = blockIdx.x * 256 + threadIdx.x;
    if (i < NB) score1[i] = 1.f - expf(-0.5f * g_sc1[i]);
    if (i < NB * M2) score2[i] = 1.f - expf(-0.5f * g_sc2[i]);
}

// ------------------------------------------------ gt MLP (f32x2, row pairs)
__global__ void __launch_bounds__(256) gt_kernel(
    const float* __restrict__ gt,
    const float* __restrict__ w1, const float* __restrict__ b1,
    const float* __restrict__ w2, const float* __restrict__ b2)
{
    __shared__ float rsT[256][20];
    __shared__ float g1T[256][20];
    int tid = threadIdx.x, r0 = blockIdx.x * 16;

    #pragma unroll
    for (int i = 0; i < 16; i++)
        rsT[tid][i] = gt[(size_t)(r0 + i) * CH + tid];
    __syncthreads();

    u64 acc[8];
    {
        u64 bb = pk2(b1[tid]);
        #pragma unroll
        for (int j = 0; j < 8; j++) acc[j] = bb;
        for (int c = 0; c < CH; c++) {
            u64 w = pk2(w1[c * CH + tid]);
            const ulonglong2* rp = (const ulonglong2*)&rsT[c][0];
            #pragma unroll
            for (int q = 0; q < 4; q++) {
                ulonglong2 a2 = rp[q];
                FMA2(acc[2 * q + 0], a2.x, w);
                FMA2(acc[2 * q + 1], a2.y, w);
            }
        }
    }
    #pragma unroll
    for (int j = 0; j < 8; j++) {
        float lo, hi; unpk2(acc[j], lo, hi);
        g1T[tid][2 * j]     = fmaxf(lo, 0.f);
        g1T[tid][2 * j + 1] = fmaxf(hi, 0.f);
    }
    if ((r0 & 511) == 0)
        g_gt1_0[(r0 >> 9) * CH + tid] = fmaxf(__uint_as_float((unsigned int)acc[0]), 0.f);
    __syncthreads();

    {
        u64 bb = pk2(b2[tid]);
        #pragma unroll
        for (int j = 0; j < 8; j++) acc[j] = bb;
        for (int c = 0; c < CH; c++) {
            u64 w = pk2(w2[c * CH + tid]);
            const ulonglong2* rp = (const ulonglong2*)&g1T[c][0];
            #pragma unroll
            for (int q = 0; q < 4; q++) {
                ulonglong2 a2 = rp[q];
                FMA2(acc[2 * q + 0], a2.x, w);
                FMA2(acc[2 * q + 1], a2.y, w);
            }
        }
    }
    #pragma unroll
    for (int j = 0; j < 8; j++) {
        float lo, hi; unpk2(acc[j], lo, hi);
        g_gt2[(size_t)(r0 + 2 * j)     * CH + tid] = fmaxf(lo, 0.f);
        g_gt2[(size_t)(r0 + 2 * j + 1) * CH + tid] = fmaxf(hi, 0.f);
    }
}

// ------------------------------------- per-row attention dots (streaming)
__global__ void __launch_bounds__(256) rowdot_kernel(
    const float* __restrict__ x, const float* __restrict__ w_att)
{
    __shared__ float wa_s[1024];
    int tid = threadIdx.x;
    *(float4*)&wa_s[tid * 4] = *(const float4*)&w_att[tid * 4];
    __syncthreads();
    int b = blockIdx.y;
    int r = blockIdx.x * 8 + (tid >> 5);
    if (r >= LEN1) return;
    int lane = tid & 31;
    const float* row = x + ((size_t)b * LEN1 + r) * CH;
    float s0 = 0.f, s1 = 0.f, s2 = 0.f, s3 = 0.f;
    #pragma unroll
    for (int j = 0; j < 8; j++) {
        int c = lane + 32 * j;
        float v = row[c];
        float4 w = *(const float4*)&wa_s[c * 4];
        s0 = fmaf(v, w.x, s0); s1 = fmaf(v, w.y, s1);
        s2 = fmaf(v, w.z, s2); s3 = fmaf(v, w.w, s3);
    }
    #pragma unroll
    for (int s = 16; s > 0; s >>= 1) {
        s0 += __shfl_xor_sync(0xffffffff, s0, s);
        s1 += __shfl_xor_sync(0xffffffff, s1, s);
        s2 += __shfl_xor_sync(0xffffffff, s2, s);
        s3 += __shfl_xor_sync(0xffffffff, s3, s);
    }
    if (lane < 4) {
        float v = (lane == 0) ? s0 : (lane == 1) ? s1 : (lane == 2) ? s2 : s3;
        g_rowdot[((size_t)b * LEN1 + r) * 4 + lane] = v;
    }
}

// ------------------------- softmax over 8 nodes + score-accumulator init
__global__ void __launch_bounds__(256) attn_softmax_kernel(const float* __restrict__ b_att)
{
    int tid = threadIdx.x, b = blockIdx.y;
    int m = blockIdx.x * 8 + (tid >> 5);
    if (blockIdx.x == 0 && tid == 0) g_sc1[b] = 0.f;
    int zi = blockIdx.x * 256 + tid;
    if (zi < M2) g_sc2[(size_t)b * M2 + zi] = 0.f;
    if (m >= M1) return;
    int lane = tid & 31;
    int h = lane & 3;
    float lg = g_rowdot[((size_t)b * LEN1 + m) * 4 + h]
             + g_rowdot[((size_t)b * LEN1 + 8 * m + 1) * 4 + lane]
             + b_att[h];
    float mx = lg;
    #pragma unroll
    for (int msk = 4; msk <= 16; msk <<= 1)
        mx = fmaxf(mx, __shfl_xor_sync(0xffffffff, mx, msk));
    float e = expf(lg - mx);
    float sum = e;
    #pragma unroll
    for (int msk = 4; msk <= 16; msk <<= 1)
        sum += __shfl_xor_sync(0xffffffff, sum, msk);
    g_attn[((size_t)b * M1 + m) * 32 + lane] = e / sum;
}

// ----------------------------- fused conv (one group per block, f32x2 GEMM)
// 128 threads, P=128. Per-thread tile: 8 positions x 8 outputs (output-packed).
// Per k per warp: 4 LDS + 8 MOV + 32 FMA2 — LDS demand below FMA2 pipe.
#define NT 128

__device__ __forceinline__ void load_w64(float (*Bs)[68], const float* __restrict__ base,
                                         int rstride, int tid)
{
    int r = tid >> 1, f = tid & 1;           // 64 rows (outputs), 2 threads/row
    const float* rp = base + (size_t)r * rstride;
    #pragma unroll
    for (int i = 0; i < 8; i++) {
        int kq = (f + i * 2) * 4;
        float4 t = *(const float4*)(rp + kq);
        Bs[kq + 0][r] = t.x; Bs[kq + 1][r] = t.y;
        Bs[kq + 2][r] = t.z; Bs[kq + 3][r] = t.w;
    }
}

// 8 positions x 8 outputs, outputs packed in u64 pairs
template<int P>
__device__ __forceinline__ void mma8x8(const float (*As)[P + 8], const float (*Bs)[68],
                                       u64 acc[8][4], int p0, int o0)
{
    #pragma unroll 4
    for (int k = 0; k < 64; k++) {
        float4 a0 = *(const float4*)&As[k][p0];
        float4 a1 = *(const float4*)&As[k][p0 + 4];
        ulonglong2 w0 = *(const ulonglong2*)&Bs[k][o0];
        ulonglong2 w1 = *(const ulonglong2*)&Bs[k][o0 + 32];
        u64 ap[8] = { pk2(a0.x), pk2(a0.y), pk2(a0.z), pk2(a0.w),
                      pk2(a1.x), pk2(a1.y), pk2(a1.z), pk2(a1.w) };
        #pragma unroll
        for (int p = 0; p < 8; p++) {
            FMA2(acc[p][0], w0.x, ap[p]);
            FMA2(acc[p][1], w0.y, ap[p]);
            FMA2(acc[p][2], w1.x, ap[p]);
            FMA2(acc[p][3], w1.y, ap[p]);
        }
    }
}

// 4 positions x 8 outputs (for src halves)
template<int P>
__device__ __forceinline__ void mma4x8(const float (*As)[P + 8], const float (*Bs)[68],
                                       u64 acc[4][4], int p0h, int o0)
{
    #pragma unroll 4
    for (int k = 0; k < 64; k++) {
        float4 a0 = *(const float4*)&As[k][p0h];
        ulonglong2 w0 = *(const ulonglong2*)&Bs[k][o0];
        ulonglong2 w1 = *(const ulonglong2*)&Bs[k][o0 + 32];
        u64 ap[4] = { pk2(a0.x), pk2(a0.y), pk2(a0.z), pk2(a0.w) };
        #pragma unroll
        for (int p = 0; p < 4; p++) {
            FMA2(acc[p][0], w0.x, ap[p]);
            FMA2(acc[p][1], w0.y, ap[p]);
            FMA2(acc[p][2], w1.x, ap[p]);
            FMA2(acc[p][3], w1.y, ap[p]);
        }
    }
}

template<int P, int STAGE>
__global__ void __launch_bounds__(NT) conv_fused_kernel(
    const float* __restrict__ x_in,
    const float* __restrict__ w_node, const float* __restrict__ b_node,
    const float* __restrict__ w_src,  const float* __restrict__ b_src,
    float* __restrict__ outp)
{
    constexpr int M  = (STAGE == 1) ? M1 : M2;
    constexpr int LS = (STAGE == 1) ? LEN1 : M1;
    const float* x   = (STAGE == 1) ? x_in : g_out1;
    const float* gtv = (STAGE == 1) ? g_gt1_0 : g_gt2;
    float*       out = (STAGE == 1) ? g_out1 : outp;

    extern __shared__ float smem[];
    float (*As)[P + 8]  = (float(*)[P + 8])smem;
    float (*Bs)[68]     = (float(*)[68])(smem + 64 * (P + 8));
    float (*attn_s)[8]  = (float(*)[8])(smem + 64 * (P + 8) + 64 * 68);
    float (*s_red)[8]   = (float(*)[8])(smem + 64 * (P + 8) + 64 * 68 + P * 8);

    int tid = threadIdx.x;
    int og = tid & 7, pg = tid >> 3;          // 8 og x 16 pg
    int o0 = og * 4;                          // outputs {o0..o0+3, o0+32..o0+35}
    int p0 = pg * 8;                          // positions p0..p0+7
    int b  = blockIdx.y, g = blockIdx.z;
    int m0 = blockIdx.x * P;
    int vrows = M - m0; if (vrows > P) vrows = P;
    int c0 = g * 64;

    for (int i = tid; i < P * 8; i += NT) {
        int p = i >> 3, n = i & 7;
        attn_s[p][n] = (p < vrows)
            ? g_attn[((size_t)b * M1 + m0 + p) * 32 + n * 4 + g] : 0.f;
    }
    __syncthreads();

    const float* node_base = x + ((size_t)b * LS + 8 * (size_t)m0 + 1) * CH + c0;
    const float* src_base  = x + ((size_t)b * LS + m0) * CH + c0;

    u64 accN[8][4];
    {
        ulonglong2 bn0 = *(const ulonglong2*)&b_node[c0 + o0];
        ulonglong2 bn1 = *(const ulonglong2*)&b_node[c0 + o0 + 32];
        #pragma unroll
        for (int p = 0; p < 8; p++) {
            accN[p][0] = bn0.x; accN[p][1] = bn0.y;
            accN[p][2] = bn1.x; accN[p][3] = bn1.y;
        }
    }

    // node conv: K = 256 (ci*4 + t), 4 chunks of 64
    for (int kc = 0; kc < 4; kc++) {
        __syncthreads();
        #pragma unroll
        for (int u = 0; u < P * 4 / NT; u++) {
            int it = tid + u * NT;
            int p = it >> 2, t = it & 3;
            bool val = p < vrows;
            float a0 = val ? attn_s[p][2 * t]     : 0.f;
            float a1 = val ? attn_s[p][2 * t + 1] : 0.f;
            const float* r0p = node_base + (size_t)(8 * p + 2 * t) * CH + kc * 16;
            const float* r1p = r0p + CH;
            #pragma unroll
            for (int q = 0; q < 4; q++) {
                float4 v0 = val ? *(const float4*)(r0p + q * 4) : make_float4(0.f,0.f,0.f,0.f);
                float4 v1 = val ? *(const float4*)(r1p + q * 4) : make_float4(0.f,0.f,0.f,0.f);
                As[(q * 4 + 0) * 4 + t][p] = a0 * v0.x + a1 * v1.x;
                As[(q * 4 + 1) * 4 + t][p] = a0 * v0.y + a1 * v1.y;
                As[(q * 4 + 2) * 4 + t][p] = a0 * v0.z + a1 * v1.z;
                As[(q * 4 + 3) * 4 + t][p] = a0 * v0.w + a1 * v1.w;
            }
        }
        load_w64(Bs, w_node + (size_t)c0 * 256 + kc * 64, 256, tid);
        __syncthreads();
        mma8x8<P>(As, Bs, accN, p0, o0);
    }

    // src conv: K = 64. Thread = one row (tid < P == NT).
    __syncthreads();
    {
        int p = tid;
        bool val = p < vrows;
        const float* rp = src_base + (size_t)p * CH;
        #pragma unroll
        for (int q = 0; q < 16; q++) {
            float4 v = val ? *(const float4*)(rp + q * 4) : make_float4(0.f,0.f,0.f,0.f);
            As[q * 4 + 0][p] = v.x; As[q * 4 + 1][p] = v.y;
            As[q * 4 + 2][p] = v.z; As[q * 4 + 3][p] = v.w;
        }
    }
    load_w64(Bs, w_src + (size_t)c0 * 64, 64, tid);
    __syncthreads();

    ulonglong2 bs0 = *(const ulonglong2*)&b_src[c0 + o0];
    ulonglong2 bs1 = *(const ulonglong2*)&b_src[c0 + o0 + 32];

    for (int half = 0; half < 2; half++) {
        u64 accS[4][4];
        #pragma unroll
        for (int p = 0; p < 4; p++) {
            accS[p][0] = bs0.x; accS[p][1] = bs0.y;
            accS[p][2] = bs1.x; accS[p][3] = bs1.y;
        }
        mma4x8<P>(As, Bs, accS, p0 + 4 * half, o0);

        // epilogue for positions 4*half .. 4*half+3
        #pragma unroll
        for (int pi = 0; pi < 4; pi++) {
            int pp = 4 * half + pi;
            int mg = m0 + p0 + pp;
            float n[8], s[8];
            unpk2(accN[pp][0], n[0], n[1]); unpk2(accN[pp][1], n[2], n[3]);
            unpk2(accN[pp][2], n[4], n[5]); unpk2(accN[pp][3], n[6], n[7]);
            unpk2(accS[pi][0], s[0], s[1]); unpk2(accS[pi][1], s[2], s[3]);
            unpk2(accS[pi][2], s[4], s[5]); unpk2(accS[pi][3], s[6], s[7]);
            #pragma unroll
            for (int o = 0; o < 8; o++) { n[o] = fmaxf(n[o], 0.f); s[o] = fmaxf(s[o], 0.f); }
            if (mg < M) {
                float* op = &out[((size_t)b * M + mg) * CH + c0];
                *(float4*)(op + o0)      = make_float4(n[0]+s[0], n[1]+s[1], n[2]+s[2], n[3]+s[3]);
                *(float4*)(op + o0 + 32) = make_float4(n[4]+s[4], n[5]+s[5], n[6]+s[6], n[7]+s[7]);
                if (STAGE == 2) {
                    const float* gp = &gtv[((size_t)b * M + mg) * CH + c0];
                    float4 g0 = *(const float4*)(gp + o0);
                    float4 g1 = *(const float4*)(gp + o0 + 32);
                    float d, S = 0.f;
                    d = g0.x - n[0]; S += d*d;  d = g0.y - n[1]; S += d*d;
                    d = g0.z - n[2]; S += d*d;  d = g0.w - n[3]; S += d*d;
                    d = g1.x - n[4]; S += d*d;  d = g1.y - n[5]; S += d*d;
                    d = g1.z - n[6]; S += d*d;  d = g1.w - n[7]; S += d*d;
                    s_red[p0 + pp][og] = S;
                } else if (mg == 0) {
                    const float* gp = &gtv[b * CH + c0];
                    float4 g0 = *(const float4*)(gp + o0);
                    float4 g1 = *(const float4*)(gp + o0 + 32);
                    float d, S = 0.f;
                    d = g0.x - n[0]; S += d*d;  d = g0.y - n[1]; S += d*d;
                    d = g0.z - n[2]; S += d*d;  d = g0.w - n[3]; S += d*d;
                    d = g1.x - n[4]; S += d*d;  d = g1.y - n[5]; S += d*d;
                    d = g1.z - n[6]; S += d*d;  d = g1.w - n[7]; S += d*d;
                    atomicAdd(&g_sc1[b], S);
                }
            }
        }
    }

    if (STAGE == 2) {
        __syncthreads();
        if (tid < P) {
            float S = 0.f;
            #pragma unroll
            for (int o = 0; o < 8; o++) S += s_red[tid][o];
            atomicAdd(&g_sc2[(size_t)b * M2 + m0 + tid], S);
        }
    }
}

extern "C" void kernel_launch(void* const* d_in, const int* in_sizes, int n_in,
                              void* d_out, int out_size)
{
    const float* input  = (const float*)d_in[0];
    const float* gt     = (const float*)d_in[1];
    const float* w_att  = (const float*)d_in[2];
    const float* b_att  = (const float*)d_in[3];
    const float* w_gt1  = (const float*)d_in[4];
    const float* b_gt1  = (const float*)d_in[5];
    const float* w_gt2  = (const float*)d_in[6];
    const float* b_gt2  = (const float*)d_in[7];
    const float* w_agg1 = (const float*)d_in[8];
    const float* b_agg1 = (const float*)d_in[9];
    const float* w_src1 = (const float*)d_in[10];
    const float* b_src1 = (const float*)d_in[11];
    const float* w_agg2 = (const float*)d_in[12];
    const float* b_agg2 = (const float*)d_in[13];
    const float* w_src2 = (const float*)d_in[14];
    const float* b_src2 = (const float*)d_in[15];

    float* out    = (float*)d_out;                 // (B*512, 256)
    float* score1 = out + (size_t)NB * M2 * CH;    // (B,)
    float* score2 = score1 + NB;                   // (B*512,)

    constexpr int P = 128;
    constexpr int SMEM_CONV = (64 * (P + 8) + 64 * 68 + P * 8 + P * 8) * 4;  // 60416 B
    cudaFuncSetAttribute(conv_fused_kernel<P, 1>,
                         cudaFuncAttributeMaxDynamicSharedMemorySize, SMEM_CONV);
    cudaFuncSetAttribute(conv_fused_kernel<P, 2>,
                         cudaFuncAttributeMaxDynamicSharedMemorySize, SMEM_CONV);

    // conv1 at captured launch index 3 (for ncu -s/-c), dependencies intact:
    // rowdot -> softmax(+score init) -> gt -> conv1 -> conv2 -> finalize
    rowdot_kernel<<<dim3((LEN1 + 7) / 8, NB), 256>>>(input, w_att);
    attn_softmax_kernel<<<dim3((M1 + 7) / 8, NB), 256>>>(b_att);
    gt_kernel<<<NB * M2 / 16, 256>>>(gt, w_gt1, b_gt1, w_gt2, b_gt2);
    conv_fused_kernel<P, 1><<<dim3((M1 + P - 1) / P, NB, 4), NT, SMEM_CONV>>>(
        input, w_agg1, b_agg1, w_src1, b_src1, nullptr);
    conv_fused_kernel<P, 2><<<dim3(M2 / P, NB, 4), NT, SMEM_CONV>>>(
        input, w_agg2, b_agg2, w_src2, b_src2, out);
    finalize_kernel<<<(NB * M2 + 255) / 256, 256>>>(score1, score2);
}

// round 10
// speedup vs baseline: 1.3221x; 1.3221x over previous
#include <cuda_runtime.h>

#define NB   4
#define LEN1 32777
#define M1   4097
#define M2   512
#define CH   256

typedef unsigned long long u64;

// ------- static scratch -------
__device__ float g_out1[NB * M1 * CH];
__device__ float g_gt2[NB * M2 * CH];
__device__ float g_gt1_0[NB * CH];
__device__ float g_attn[NB * M1 * 32];     // softmax attn, (b, m, n*4+h)
__device__ float g_rowdot[NB * LEN1 * 4];  // per-row dot with w_att
__device__ float g_sc1[NB];
__device__ float g_sc2[NB * M2];

// ---- f32x2 helpers ----
__device__ __forceinline__ u64 pk2(float v) {
    u64 r; unsigned int u = __float_as_uint(v);
    asm("mov.b64 %0, {%1, %1};" : "=l"(r) : "r"(u));
    return r;
}
__device__ __forceinline__ void unpk2(u64 v, float& lo, float& hi) {
    unsigned int a, b;
    asm("mov.b64 {%0, %1}, %2;" : "=r"(a), "=r"(b) : "l"(v));
    lo = __uint_as_float(a); hi = __uint_as_float(b);
}
#define FMA2(d, a, b) asm("fma.rn.f32x2 %0, %1, %2, %0;" : "+l"(d) : "l"(a), "l"(b))

// --------------------------------------------------------- finalize
__global__ void finalize_kernel(float* score1, float* score2) {
    int i = blockIdx.x * 256 + threadIdx.x;
    if (i < NB) score1[i] = 1.f - expf(-0.5f * g_sc1[i]);
    if (i < NB * M2) score2[i] = 1.f - expf(-0.5f * g_sc2[i]);
}

// ------------------------------------------------ gt MLP (f32x2, row pairs)
__global__ void __launch_bounds__(256) gt_kernel(
    const float* __restrict__ gt,
    const float* __restrict__ w1, const float* __restrict__ b1,
    const float* __restrict__ w2, const float* __restrict__ b2)
{
    __shared__ float rsT[256][20];
    __shared__ float g1T[256][20];
    int tid = threadIdx.x, r0 = blockIdx.x * 16;

    #pragma unroll
    for (int i = 0; i < 16; i++)
        rsT[tid][i] = gt[(size_t)(r0 + i) * CH + tid];
    __syncthreads();

    u64 acc[8];
    {
        u64 bb = pk2(b1[tid]);
        #pragma unroll
        for (int j = 0; j < 8; j++) acc[j] = bb;
        for (int c = 0; c < CH; c++) {
            u64 w = pk2(w1[c * CH + tid]);
            const ulonglong2* rp = (const ulonglong2*)&rsT[c][0];
            #pragma unroll
            for (int q = 0; q < 4; q++) {
                ulonglong2 a2 = rp[q];
                FMA2(acc[2 * q + 0], a2.x, w);
                FMA2(acc[2 * q + 1], a2.y, w);
            }
        }
    }
    #pragma unroll
    for (int j = 0; j < 8; j++) {
        float lo, hi; unpk2(acc[j], lo, hi);
        g1T[tid][2 * j]     = fmaxf(lo, 0.f);
        g1T[tid][2 * j + 1] = fmaxf(hi, 0.f);
    }
    if ((r0 & 511) == 0)
        g_gt1_0[(r0 >> 9) * CH + tid] = fmaxf(__uint_as_float((unsigned int)acc[0]), 0.f);
    __syncthreads();

    {
        u64 bb = pk2(b2[tid]);
        #pragma unroll
        for (int j = 0; j < 8; j++) acc[j] = bb;
        for (int c = 0; c < CH; c++) {
            u64 w = pk2(w2[c * CH + tid]);
            const ulonglong2* rp = (const ulonglong2*)&g1T[c][0];
            #pragma unroll
            for (int q = 0; q < 4; q++) {
                ulonglong2 a2 = rp[q];
                FMA2(acc[2 * q + 0], a2.x, w);
                FMA2(acc[2 * q + 1], a2.y, w);
            }
        }
    }
    #pragma unroll
    for (int j = 0; j < 8; j++) {
        float lo, hi; unpk2(acc[j], lo, hi);
        g_gt2[(size_t)(r0 + 2 * j)     * CH + tid] = fmaxf(lo, 0.f);
        g_gt2[(size_t)(r0 + 2 * j + 1) * CH + tid] = fmaxf(hi, 0.f);
    }
}

// ------------------------------------- per-row attention dots (streaming)
__global__ void __launch_bounds__(256) rowdot_kernel(
    const float* __restrict__ x, const float* __restrict__ w_att)
{
    __shared__ float wa_s[1024];
    int tid = threadIdx.x;
    *(float4*)&wa_s[tid * 4] = *(const float4*)&w_att[tid * 4];
    __syncthreads();
    int b = blockIdx.y;
    int r = blockIdx.x * 8 + (tid >> 5);
    if (r >= LEN1) return;
    int lane = tid & 31;
    const float* row = x + ((size_t)b * LEN1 + r) * CH;
    float s0 = 0.f, s1 = 0.f, s2 = 0.f, s3 = 0.f;
    #pragma unroll
    for (int j = 0; j < 8; j++) {
        int c = lane + 32 * j;
        float v = row[c];
        float4 w = *(const float4*)&wa_s[c * 4];
        s0 = fmaf(v, w.x, s0); s1 = fmaf(v, w.y, s1);
        s2 = fmaf(v, w.z, s2); s3 = fmaf(v, w.w, s3);
    }
    #pragma unroll
    for (int s = 16; s > 0; s >>= 1) {
        s0 += __shfl_xor_sync(0xffffffff, s0, s);
        s1 += __shfl_xor_sync(0xffffffff, s1, s);
        s2 += __shfl_xor_sync(0xffffffff, s2, s);
        s3 += __shfl_xor_sync(0xffffffff, s3, s);
    }
    if (lane < 4) {
        float v = (lane == 0) ? s0 : (lane == 1) ? s1 : (lane == 2) ? s2 : s3;
        g_rowdot[((size_t)b * LEN1 + r) * 4 + lane] = v;
    }
}

// ------------------------- softmax over 8 nodes + score-accumulator init
__global__ void __launch_bounds__(256) attn_softmax_kernel(const float* __restrict__ b_att)
{
    int tid = threadIdx.x, b = blockIdx.y;
    int m = blockIdx.x * 8 + (tid >> 5);
    if (blockIdx.x == 0 && tid == 0) g_sc1[b] = 0.f;
    int zi = blockIdx.x * 256 + tid;
    if (zi < M2) g_sc2[(size_t)b * M2 + zi] = 0.f;
    if (m >= M1) return;
    int lane = tid & 31;
    int h = lane & 3;
    float lg = g_rowdot[((size_t)b * LEN1 + m) * 4 + h]
             + g_rowdot[((size_t)b * LEN1 + 8 * m + 1) * 4 + lane]
             + b_att[h];
    float mx = lg;
    #pragma unroll
    for (int msk = 4; msk <= 16; msk <<= 1)
        mx = fmaxf(mx, __shfl_xor_sync(0xffffffff, mx, msk));
    float e = expf(lg - mx);
    float sum = e;
    #pragma unroll
    for (int msk = 4; msk <= 16; msk <<= 1)
        sum += __shfl_xor_sync(0xffffffff, sum, msk);
    g_attn[((size_t)b * M1 + m) * 32 + lane] = e / sum;
}

// ----------------------------- fused conv (one group per block, f32x2 GEMM)
// 256 threads, P=128, per-thread 4 pos x 8 out. Build phase uses coalesced
// LDGs (8 lines/warp-LDG) with XOR p-swizzle (px = p ^ 4*(k>>4)) on As.
#define NT 256

__device__ __forceinline__ void load_w64(float (*Bs)[68], const float* __restrict__ base,
                                         int rstride, int tid)
{
    int r = tid >> 2, f = tid & 3;            // 64 rows (outputs), 4 threads/row
    const float* rp = base + (size_t)r * rstride;
    #pragma unroll
    for (int i = 0; i < 4; i++) {
        int kq = (f + i * 4) * 4;
        float4 t = *(const float4*)(rp + kq);
        Bs[kq + 0][r] = t.x; Bs[kq + 1][r] = t.y;
        Bs[kq + 2][r] = t.z; Bs[kq + 3][r] = t.w;
    }
}

template<int P>
__device__ __forceinline__ void mma_block(const float (*As)[P + 8], const float (*Bs)[68],
                                          u64 acc[4][4], int p0, int o0)
{
    #pragma unroll 16
    for (int k = 0; k < 64; k++) {
        int px = p0 ^ ((k & 48) >> 2);        // inverse of the build swizzle
        float4 av = *(const float4*)&As[k][px];
        ulonglong2 w0 = *(const ulonglong2*)&Bs[k][o0];
        ulonglong2 w1 = *(const ulonglong2*)&Bs[k][o0 + 32];
        u64 ap0 = pk2(av.x), ap1 = pk2(av.y), ap2 = pk2(av.z), ap3 = pk2(av.w);
        FMA2(acc[0][0], w0.x, ap0); FMA2(acc[0][1], w0.y, ap0);
        FMA2(acc[0][2], w1.x, ap0); FMA2(acc[0][3], w1.y, ap0);
        FMA2(acc[1][0], w0.x, ap1); FMA2(acc[1][1], w0.y, ap1);
        FMA2(acc[1][2], w1.x, ap1); FMA2(acc[1][3], w1.y, ap1);
        FMA2(acc[2][0], w0.x, ap2); FMA2(acc[2][1], w0.y, ap2);
        FMA2(acc[2][2], w1.x, ap2); FMA2(acc[2][3], w1.y, ap2);
        FMA2(acc[3][0], w0.x, ap3); FMA2(acc[3][1], w0.y, ap3);
        FMA2(acc[3][2], w1.x, ap3); FMA2(acc[3][3], w1.y, ap3);
    }
}

template<int P, int STAGE>
__global__ void __launch_bounds__(NT, 2) conv_fused_kernel(
    const float* __restrict__ x_in,
    const float* __restrict__ w_node, const float* __restrict__ b_node,
    const float* __restrict__ w_src,  const float* __restrict__ b_src,
    float* __restrict__ outp)
{
    constexpr int M  = (STAGE == 1) ? M1 : M2;
    constexpr int LS = (STAGE == 1) ? LEN1 : M1;
    const float* x   = (STAGE == 1) ? x_in : g_out1;
    const float* gtv = (STAGE == 1) ? g_gt1_0 : g_gt2;
    float*       out = (STAGE == 1) ? g_out1 : outp;

    extern __shared__ float smem[];
    float (*As)[P + 8]  = (float(*)[P + 8])smem;
    float (*Bs)[68]     = (float(*)[68])(smem + 64 * (P + 8));
    float (*attn_s)[8]  = (float(*)[8])(smem + 64 * (P + 8) + 64 * 68);
    float (*s_red)[8]   = (float(*)[8])(smem + 64 * (P + 8) + 64 * 68 + P * 8);

    int tid = threadIdx.x;
    int og = tid & 7, pg = tid >> 3;          // 8 og x 32 pg
    int o0 = og * 4;                          // outputs {o0..o0+3, o0+32..o0+35}
    int p0 = pg * 4;                          // positions p0..p0+3
    int b  = blockIdx.y, g = blockIdx.z;
    int m0 = blockIdx.x * P;
    int vrows = M - m0; if (vrows > P) vrows = P;
    int c0 = g * 64;

    for (int i = tid; i < P * 8; i += NT) {
        int p = i >> 3, n = i & 7;
        attn_s[p][n] = (p < vrows)
            ? g_attn[((size_t)b * M1 + m0 + p) * 32 + n * 4 + g] : 0.f;
    }
    __syncthreads();

    const float* node_base = x + ((size_t)b * LS + 8 * (size_t)m0 + 1) * CH + c0;
    const float* src_base  = x + ((size_t)b * LS + m0) * CH + c0;

    u64 accN[4][4], accS[4][4];
    {
        ulonglong2 bn0 = *(const ulonglong2*)&b_node[c0 + o0];
        ulonglong2 bn1 = *(const ulonglong2*)&b_node[c0 + o0 + 32];
        ulonglong2 bs0 = *(const ulonglong2*)&b_src[c0 + o0];
        ulonglong2 bs1 = *(const ulonglong2*)&b_src[c0 + o0 + 32];
        #pragma unroll
        for (int p = 0; p < 4; p++) {
            accN[p][0] = bn0.x; accN[p][1] = bn0.y; accN[p][2] = bn1.x; accN[p][3] = bn1.y;
            accS[p][0] = bs0.x; accS[p][1] = bs0.y; accS[p][2] = bs1.x; accS[p][3] = bs1.y;
        }
    }

    // node conv: K = 256 (k = ci*4 + t), 4 chunks of 64.
    // Coalesced build: lane = (quad fastest); warp-LDG touches 8 lines.
    for (int kc = 0; kc < 4; kc++) {
        __syncthreads();
        #pragma unroll
        for (int u = 0; u < 8; u++) {
            int q  = tid & 3;                  // 16B quad within the 64B row chunk
            int pi = (tid >> 2) + u * 64;      // 0..511 = (p, t)
            int p  = pi >> 2, t = pi & 3;
            bool val = p < vrows;
            float a0 = val ? attn_s[p][2 * t]     : 0.f;
            float a1 = val ? attn_s[p][2 * t + 1] : 0.f;
            const float* r0p = node_base + (size_t)(8 * p + 2 * t) * CH + kc * 16 + q * 4;
            float4 v0 = val ? *(const float4*)r0p        : make_float4(0.f,0.f,0.f,0.f);
            float4 v1 = val ? *(const float4*)(r0p + CH) : make_float4(0.f,0.f,0.f,0.f);
            int px = p ^ (q << 2);             // XOR swizzle (k>>4 == q here)
            As[(q * 4 + 0) * 4 + t][px] = a0 * v0.x + a1 * v1.x;
            As[(q * 4 + 1) * 4 + t][px] = a0 * v0.y + a1 * v1.y;
            As[(q * 4 + 2) * 4 + t][px] = a0 * v0.z + a1 * v1.z;
            As[(q * 4 + 3) * 4 + t][px] = a0 * v0.w + a1 * v1.w;
        }
        load_w64(Bs, w_node + (size_t)c0 * 256 + kc * 64, 256, tid);
        __syncthreads();
        mma_block<P>(As, Bs, accN, p0, o0);
    }

    // src conv: K = 64 (k = qq*4 + i), same swizzle (k>>4 == qq>>2)
    __syncthreads();
    #pragma unroll
    for (int u = 0; u < 8; u++) {
        int it = tid + u * NT;
        int p  = it & (P - 1);
        int qq = it >> 7;                      // 0..15
        float4 v = (p < vrows) ? *(const float4*)(src_base + (size_t)p * CH + qq * 4)
                               : make_float4(0.f, 0.f, 0.f, 0.f);
        int px = p ^ (qq & 12);
        As[qq * 4 + 0][px] = v.x; As[qq * 4 + 1][px] = v.y;
        As[qq * 4 + 2][px] = v.z; As[qq * 4 + 3][px] = v.w;
    }
    load_w64(Bs, w_src + (size_t)c0 * 64, 64, tid);
    __syncthreads();
    mma_block<P>(As, Bs, accS, p0, o0);

    // epilogue
    #pragma unroll
    for (int pi = 0; pi < 4; pi++) {
        int mg = m0 + p0 + pi;
        float n[8], s[8];
        unpk2(accN[pi][0], n[0], n[1]); unpk2(accN[pi][1], n[2], n[3]);
        unpk2(accN[pi][2], n[4], n[5]); unpk2(accN[pi][3], n[6], n[7]);
        unpk2(accS[pi][0], s[0], s[1]); unpk2(accS[pi][1], s[2], s[3]);
        unpk2(accS[pi][2], s[4], s[5]); unpk2(accS[pi][3], s[6], s[7]);
        #pragma unroll
        for (int o = 0; o < 8; o++) { n[o] = fmaxf(n[o], 0.f); s[o] = fmaxf(s[o], 0.f); }
        if (mg < M) {
            float* op = &out[((size_t)b * M + mg) * CH + c0];
            *(float4*)(op + o0)      = make_float4(n[0]+s[0], n[1]+s[1], n[2]+s[2], n[3]+s[3]);
            *(float4*)(op + o0 + 32) = make_float4(n[4]+s[4], n[5]+s[5], n[6]+s[6], n[7]+s[7]);
            if (STAGE == 2) {
                const float* gp = &gtv[((size_t)b * M + mg) * CH + c0];
                float4 g0 = *(const float4*)(gp + o0);
                float4 g1 = *(const float4*)(gp + o0 + 32);
                float d, S = 0.f;
                d = g0.x - n[0]; S += d*d;  d = g0.y - n[1]; S += d*d;
                d = g0.z - n[2]; S += d*d;  d = g0.w - n[3]; S += d*d;
                d = g1.x - n[4]; S += d*d;  d = g1.y - n[5]; S += d*d;
                d = g1.z - n[6]; S += d*d;  d = g1.w - n[7]; S += d*d;
                s_red[p0 + pi][og] = S;
            } else if (mg == 0) {
                const float* gp = &gtv[b * CH + c0];
                float4 g0 = *(const float4*)(gp + o0);
                float4 g1 = *(const float4*)(gp + o0 + 32);
                float d, S = 0.f;
                d = g0.x - n[0]; S += d*d;  d = g0.y - n[1]; S += d*d;
                d = g0.z - n[2]; S += d*d;  d = g0.w - n[3]; S += d*d;
                d = g1.x - n[4]; S += d*d;  d = g1.y - n[5]; S += d*d;
                d = g1.z - n[6]; S += d*d;  d = g1.w - n[7]; S += d*d;
                atomicAdd(&g_sc1[b], S);
            }
        }
    }
    if (STAGE == 2) {
        __syncthreads();
        if (tid < P) {
            float S = 0.f;
            #pragma unroll
            for (int o = 0; o < 8; o++) S += s_red[tid][o];
            atomicAdd(&g_sc2[(size_t)b * M2 + m0 + tid], S);
        }
    }
}

extern "C" void kernel_launch(void* const* d_in, const int* in_sizes, int n_in,
                              void* d_out, int out_size)
{
    const float* input  = (const float*)d_in[0];
    const float* gt     = (const float*)d_in[1];
    const float* w_att  = (const float*)d_in[2];
    const float* b_att  = (const float*)d_in[3];
    const float* w_gt1  = (const float*)d_in[4];
    const float* b_gt1  = (const float*)d_in[5];
    const float* w_gt2  = (const float*)d_in[6];
    const float* b_gt2  = (const float*)d_in[7];
    const float* w_agg1 = (const float*)d_in[8];
    const float* b_agg1 = (const float*)d_in[9];
    const float* w_src1 = (const float*)d_in[10];
    const float* b_src1 = (const float*)d_in[11];
    const float* w_agg2 = (const float*)d_in[12];
    const float* b_agg2 = (const float*)d_in[13];
    const float* w_src2 = (const float*)d_in[14];
    const float* b_src2 = (const float*)d_in[15];

    float* out    = (float*)d_out;                 // (B*512, 256)
    float* score1 = out + (size_t)NB * M2 * CH;    // (B,)
    float* score2 = score1 + NB;                   // (B*512,)

    constexpr int P = 128;
    constexpr int SMEM_CONV = (64 * (P + 8) + 64 * 68 + P * 8 + P * 8) * 4;  // 60416 B
    cudaFuncSetAttribute(conv_fused_kernel<P, 1>,
                         cudaFuncAttributeMaxDynamicSharedMemorySize, SMEM_CONV);
    cudaFuncSetAttribute(conv_fused_kernel<P, 2>,
                         cudaFuncAttributeMaxDynamicSharedMemorySize, SMEM_CONV);

    // conv1 at captured launch index 3 (for ncu -s/-c), dependencies intact:
    // rowdot -> softmax(+score init) -> gt -> conv1 -> conv2 -> finalize
    rowdot_kernel<<<dim3((LEN1 + 7) / 8, NB), 256>>>(input, w_att);
    attn_softmax_kernel<<<dim3((M1 + 7) / 8, NB), 256>>>(b_att);
    gt_kernel<<<NB * M2 / 16, 256>>>(gt, w_gt1, b_gt1, w_gt2, b_gt2);
    conv_fused_kernel<P, 1><<<dim3((M1 + P - 1) / P, NB, 4), NT, SMEM_CONV>>>(
        input, w_agg1, b_agg1, w_src1, b_src1, nullptr);
    conv_fused_kernel<P, 2><<<dim3(M2 / P, NB, 4), NT, SMEM_CONV>>>(
        input, w_agg2, b_agg2, w_src2, b_src2, out);
    finalize_kernel<<<(NB * M2 + 255) / 256, 256>>>(score1, score2);
}

// round 12
// speedup vs baseline: 1.3792x; 1.0432x over previous
#include <cuda_runtime.h>
#include <cuda_bf16.h>
#include <mma.h>

#define NB   4
#define LEN1 32777
#define M1   4097
#define M2   512
#define CH   256

typedef unsigned long long u64;
typedef unsigned int u32;
using namespace nvcuda;

// ------- static scratch -------
__device__ float g_out1[NB * M1 * CH];
__device__ float g_gt2[NB * M2 * CH];
__device__ float g_gt1_0[NB * CH];
__device__ float g_attn[NB * M1 * 32];
__device__ float g_rowdot[NB * LEN1 * 4];
__device__ float g_sc1[NB];
__device__ float g_sc2[NB * M2];

// ---- f32x2 helpers (gt kernel) ----
__device__ __forceinline__ u64 pk2(float v) {
    u64 r; u32 u = __float_as_uint(v);
    asm("mov.b64 %0, {%1, %1};" : "=l"(r) : "r"(u));
    return r;
}
__device__ __forceinline__ void unpk2(u64 v, float& lo, float& hi) {
    u32 a, b;
    asm("mov.b64 {%0, %1}, %2;" : "=r"(a), "=r"(b) : "l"(v));
    lo = __uint_as_float(a); hi = __uint_as_float(b);
}
#define FMA2(d, a, b) asm("fma.rn.f32x2 %0, %1, %2, %0;" : "+l"(d) : "l"(a), "l"(b))

// pack two floats to bf16x2: low 16 bits = first arg
__device__ __forceinline__ u32 pkbf(float lo_v, float hi_v) {
    u32 r;
    asm("cvt.rn.bf16x2.f32 %0, %1, %2;" : "=r"(r) : "f"(hi_v), "f"(lo_v));
    return r;
}

// split-store a quad of floats as bf16 hi + lo at byte offset boff
__device__ __forceinline__ void split4(char* hi, char* lo, int boff,
                                       float v0, float v1, float v2, float v3) {
    u32 h01 = pkbf(v0, v1), h23 = pkbf(v2, v3);
    float r0 = v0 - __uint_as_float(h01 << 16);
    float r1 = v1 - __uint_as_float(h01 & 0xffff0000u);
    float r2 = v2 - __uint_as_float(h23 << 16);
    float r3 = v3 - __uint_as_float(h23 & 0xffff0000u);
    *(uint2*)(hi + boff) = make_uint2(h01, h23);
    *(uint2*)(lo + boff) = make_uint2(pkbf(r0, r1), pkbf(r2, r3));
}
__device__ __forceinline__ void split1(char* hi, char* lo, int boff, float v) {
    u32 h = pkbf(v, 0.f);
    float r = v - __uint_as_float(h << 16);
    u32 l = pkbf(r, 0.f);
    *(unsigned short*)(hi + boff) = (unsigned short)(h & 0xffff);
    *(unsigned short*)(lo + boff) = (unsigned short)(l & 0xffff);
}

// --------------------------------------------------------- finalize
__global__ void finalize_kernel(float* score1, float* score2) {
    int i = blockIdx.x * 256 + threadIdx.x;
    if (i < NB) score1[i] = 1.f - expf(-0.5f * g_sc1[i]);
    if (i < NB * M2) score2[i] = 1.f - expf(-0.5f * g_sc2[i]);
}

// ------------------------------------------------ gt MLP (f32x2, row pairs)
__global__ void __launch_bounds__(256) gt_kernel(
    const float* __restrict__ gt,
    const float* __restrict__ w1, const float* __restrict__ b1,
    const float* __restrict__ w2, const float* __restrict__ b2)
{
    __shared__ float rsT[256][20];
    __shared__ float g1T[256][20];
    int tid = threadIdx.x, r0 = blockIdx.x * 16;

    #pragma unroll
    for (int i = 0; i < 16; i++)
        rsT[tid][i] = gt[(size_t)(r0 + i) * CH + tid];
    __syncthreads();

    u64 acc[8];
    {
        u64 bb = pk2(b1[tid]);
        #pragma unroll
        for (int j = 0; j < 8; j++) acc[j] = bb;
        for (int c = 0; c < CH; c++) {
            u64 w = pk2(w1[c * CH + tid]);
            const ulonglong2* rp = (const ulonglong2*)&rsT[c][0];
            #pragma unroll
            for (int q = 0; q < 4; q++) {
                ulonglong2 a2 = rp[q];
                FMA2(acc[2 * q + 0], a2.x, w);
                FMA2(acc[2 * q + 1], a2.y, w);
            }
        }
    }
    #pragma unroll
    for (int j = 0; j < 8; j++) {
        float lo, hi; unpk2(acc[j], lo, hi);
        g1T[tid][2 * j]     = fmaxf(lo, 0.f);
        g1T[tid][2 * j + 1] = fmaxf(hi, 0.f);
    }
    if ((r0 & 511) == 0)
        g_gt1_0[(r0 >> 9) * CH + tid] = fmaxf(__uint_as_float((u32)acc[0]), 0.f);
    __syncthreads();

    {
        u64 bb = pk2(b2[tid]);
        #pragma unroll
        for (int j = 0; j < 8; j++) acc[j] = bb;
        for (int c = 0; c < CH; c++) {
            u64 w = pk2(w2[c * CH + tid]);
            const ulonglong2* rp = (const ulonglong2*)&g1T[c][0];
            #pragma unroll
            for (int q = 0; q < 4; q++) {
                ulonglong2 a2 = rp[q];
                FMA2(acc[2 * q + 0], a2.x, w);
                FMA2(acc[2 * q + 1], a2.y, w);
            }
        }
    }
    #pragma unroll
    for (int j = 0; j < 8; j++) {
        float lo, hi; unpk2(acc[j], lo, hi);
        g_gt2[(size_t)(r0 + 2 * j)     * CH + tid] = fmaxf(lo, 0.f);
        g_gt2[(size_t)(r0 + 2 * j + 1) * CH + tid] = fmaxf(hi, 0.f);
    }
}

// ------------------------------------- per-row attention dots (streaming)
__global__ void __launch_bounds__(256) rowdot_kernel(
    const float* __restrict__ x, const float* __restrict__ w_att)
{
    __shared__ float wa_s[1024];
    int tid = threadIdx.x;
    *(float4*)&wa_s[tid * 4] = *(const float4*)&w_att[tid * 4];
    __syncthreads();
    int b = blockIdx.y;
    int r = blockIdx.x * 8 + (tid >> 5);
    if (r >= LEN1) return;
    int lane = tid & 31;
    const float* row = x + ((size_t)b * LEN1 + r) * CH;
    float s0 = 0.f, s1 = 0.f, s2 = 0.f, s3 = 0.f;
    #pragma unroll
    for (int j = 0; j < 8; j++) {
        int c = lane + 32 * j;
        float v = row[c];
        float4 w = *(const float4*)&wa_s[c * 4];
        s0 = fmaf(v, w.x, s0); s1 = fmaf(v, w.y, s1);
        s2 = fmaf(v, w.z, s2); s3 = fmaf(v, w.w, s3);
    }
    #pragma unroll
    for (int s = 16; s > 0; s >>= 1) {
        s0 += __shfl_xor_sync(0xffffffff, s0, s);
        s1 += __shfl_xor_sync(0xffffffff, s1, s);
        s2 += __shfl_xor_sync(0xffffffff, s2, s);
        s3 += __shfl_xor_sync(0xffffffff, s3, s);
    }
    if (lane < 4) {
        float v = (lane == 0) ? s0 : (lane == 1) ? s1 : (lane == 2) ? s2 : s3;
        g_rowdot[((size_t)b * LEN1 + r) * 4 + lane] = v;
    }
}

// ------------------------- softmax over 8 nodes + score-accumulator init
__global__ void __launch_bounds__(256) attn_softmax_kernel(const float* __restrict__ b_att)
{
    int tid = threadIdx.x, b = blockIdx.y;
    int m = blockIdx.x * 8 + (tid >> 5);
    if (blockIdx.x == 0 && tid == 0) g_sc1[b] = 0.f;
    int zi = blockIdx.x * 256 + tid;
    if (zi < M2) g_sc2[(size_t)b * M2 + zi] = 0.f;
    if (m >= M1) return;
    int lane = tid & 31;
    int h = lane & 3;
    float lg = g_rowdot[((size_t)b * LEN1 + m) * 4 + h]
             + g_rowdot[((size_t)b * LEN1 + 8 * m + 1) * 4 + lane]
             + b_att[h];
    float mx = lg;
    #pragma unroll
    for (int msk = 4; msk <= 16; msk <<= 1)
        mx = fmaxf(mx, __shfl_xor_sync(0xffffffff, mx, msk));
    float e = expf(lg - mx);
    float sum = e;
    #pragma unroll
    for (int msk = 4; msk <= 16; msk <<= 1)
        sum += __shfl_xor_sync(0xffffffff, sum, msk);
    g_attn[((size_t)b * M1 + m) * 32 + lane] = e / sum;
}

// ---------------- wmma bf16-split fused conv: (128 pos, 64 out) per block
// A/B split into bf16 hi+lo; 3 products (hh, hl, lh) into fp32 accumulators.
// smem bytes:
#define OF_BN   0
#define OF_BS   256
#define OF_ATT  512
#define OF_A    4608
#define OF_ALO  (OF_A + 18432)
#define OF_B    (OF_A + 36864)
#define OF_BLO  (OF_B + 9216)
#define SMEM_TOT (OF_B + 18432)

template<int STAGE>
__global__ void __launch_bounds__(256) conv_tc_kernel(
    const float* __restrict__ x_in,
    const float* __restrict__ w_node, const float* __restrict__ b_node,
    const float* __restrict__ w_src,  const float* __restrict__ b_src,
    float* __restrict__ outp)
{
    constexpr int M  = (STAGE == 1) ? M1 : M2;
    constexpr int LS = (STAGE == 1) ? LEN1 : M1;
    const float* x   = (STAGE == 1) ? x_in : g_out1;
    const float* gtv = (STAGE == 1) ? g_gt1_0 : g_gt2;
    float*       out = (STAGE == 1) ? g_out1 : outp;

    extern __shared__ char sm[];
    float* biasN = (float*)(sm + OF_BN);
    float* biasS = (float*)(sm + OF_BS);
    float (*attn_s)[8] = (float(*)[8])(sm + OF_ATT);
    char *AHI = sm + OF_A, *ALO = sm + OF_ALO;
    char *BHI = sm + OF_B, *BLO = sm + OF_BLO;

    int tid = threadIdx.x, w = tid >> 5, lane = tid & 31;
    int b = blockIdx.y, g = blockIdx.z;
    int m0 = blockIdx.x * 128;
    int vrows = M - m0; if (vrows > 128) vrows = 128;
    int c0 = g * 64;

    if (tid < 64) { biasN[tid] = b_node[c0 + tid]; biasS[tid] = b_src[c0 + tid]; }
    for (int i = tid; i < 128 * 8; i += 256) {
        int p = i >> 3, n = i & 7;
        attn_s[p][n] = (p < vrows)
            ? g_attn[((size_t)b * M1 + m0 + p) * 32 + n * 4 + g] : 0.f;
    }
    __syncthreads();

    const float* node_base = x + ((size_t)b * LS + 8 * (size_t)m0 + 1) * CH + c0;
    const float* src_base  = x + ((size_t)b * LS + m0) * CH + c0;

    wmma::fragment<wmma::accumulator, 16, 16, 16, float> accN[4], accS[4];
    #pragma unroll
    for (int j = 0; j < 4; j++) { wmma::fill_fragment(accN[j], 0.f); wmma::fill_fragment(accS[j], 0.f); }

    const __nv_bfloat16* Ah = (const __nv_bfloat16*)AHI;
    const __nv_bfloat16* Al = (const __nv_bfloat16*)ALO;
    const __nv_bfloat16* Bh = (const __nv_bfloat16*)BHI;
    const __nv_bfloat16* Bl = (const __nv_bfloat16*)BLO;

    // ---- node conv: K=256, 4 chunks of 64 (k = t*16 + cl) ----
    for (int kc = 0; kc < 4; kc++) {
        __syncthreads();
        #pragma unroll
        for (int u = 0; u < 8; u++) {
            int idx = (tid >> 2) + u * 64;
            int p = idx >> 2, t = idx & 3, q = tid & 3;
            bool val = p < vrows;
            float a0 = val ? attn_s[p][2 * t]     : 0.f;
            float a1 = val ? attn_s[p][2 * t + 1] : 0.f;
            const float* r0 = node_base + (size_t)(8 * p + 2 * t) * CH + kc * 16 + q * 4;
            float4 v0 = val ? *(const float4*)r0        : make_float4(0.f, 0.f, 0.f, 0.f);
            float4 v1 = val ? *(const float4*)(r0 + CH) : make_float4(0.f, 0.f, 0.f, 0.f);
            split4(AHI, ALO, p * 144 + (t * 16 + q * 4) * 2,
                   fmaf(a0, v0.x, a1 * v1.x), fmaf(a0, v0.y, a1 * v1.y),
                   fmaf(a0, v0.z, a1 * v1.z), fmaf(a0, v0.w, a1 * v1.w));
        }
        #pragma unroll
        for (int u = 0; u < 4; u++) {
            int it = tid + u * 256;
            int o = it >> 4, cl = it & 15;
            float4 wv = *(const float4*)(w_node + (size_t)(c0 + o) * 256 + (kc * 16 + cl) * 4);
            split1(BHI, BLO, o * 144 + (0 * 16 + cl) * 2, wv.x);
            split1(BHI, BLO, o * 144 + (1 * 16 + cl) * 2, wv.y);
            split1(BHI, BLO, o * 144 + (2 * 16 + cl) * 2, wv.z);
            split1(BHI, BLO, o * 144 + (3 * 16 + cl) * 2, wv.w);
        }
        __syncthreads();
        #pragma unroll
        for (int ks = 0; ks < 4; ks++) {
            wmma::fragment<wmma::matrix_a, 16, 16, 16, __nv_bfloat16, wmma::row_major> ah, al;
            wmma::load_matrix_sync(ah, Ah + (w * 16) * 72 + ks * 16, 72);
            wmma::load_matrix_sync(al, Al + (w * 16) * 72 + ks * 16, 72);
            #pragma unroll
            for (int j = 0; j < 4; j++) {
                wmma::fragment<wmma::matrix_b, 16, 16, 16, __nv_bfloat16, wmma::col_major> bh, bl;
                wmma::load_matrix_sync(bh, Bh + (j * 16) * 72 + ks * 16, 72);
                wmma::load_matrix_sync(bl, Bl + (j * 16) * 72 + ks * 16, 72);
                wmma::mma_sync(accN[j], ah, bh, accN[j]);
                wmma::mma_sync(accN[j], ah, bl, accN[j]);
                wmma::mma_sync(accN[j], al, bh, accN[j]);
            }
        }
    }

    // ---- src conv: K=64 (natural order) ----
    __syncthreads();
    #pragma unroll
    for (int u = 0; u < 8; u++) {
        int idx = (tid >> 2) + u * 64;
        int p = idx >> 2, qg = idx & 3, q = tid & 3;
        int qi = qg * 4 + q;
        bool val = p < vrows;
        float4 v = val ? *(const float4*)(src_base + (size_t)p * CH + qi * 4)
                       : make_float4(0.f, 0.f, 0.f, 0.f);
        split4(AHI, ALO, p * 144 + qi * 8, v.x, v.y, v.z, v.w);
    }
    #pragma unroll
    for (int u = 0; u < 4; u++) {
        int it = tid + u * 256;
        int o = it >> 4, qg = it & 15;
        float4 wv = *(const float4*)(w_src + (size_t)(c0 + o) * 64 + qg * 4);
        split4(BHI, BLO, o * 144 + qg * 8, wv.x, wv.y, wv.z, wv.w);
    }
    __syncthreads();
    #pragma unroll
    for (int ks = 0; ks < 4; ks++) {
        wmma::fragment<wmma::matrix_a, 16, 16, 16, __nv_bfloat16, wmma::row_major> ah, al;
        wmma::load_matrix_sync(ah, Ah + (w * 16) * 72 + ks * 16, 72);
        wmma::load_matrix_sync(al, Al + (w * 16) * 72 + ks * 16, 72);
        #pragma unroll
        for (int j = 0; j < 4; j++) {
            wmma::fragment<wmma::matrix_b, 16, 16, 16, __nv_bfloat16, wmma::col_major> bh, bl;
            wmma::load_matrix_sync(bh, Bh + (j * 16) * 72 + ks * 16, 72);
            wmma::load_matrix_sync(bl, Bl + (j * 16) * 72 + ks * 16, 72);
            wmma::mma_sync(accS[j], ah, bh, accS[j]);
            wmma::mma_sync(accS[j], ah, bl, accS[j]);
            wmma::mma_sync(accS[j], al, bh, accS[j]);
        }
    }
    __syncthreads();   // all warps done reading A/B smem

    // ---- epilogue: per-warp scratch in A region ----
    float* scr = (float*)(sm + OF_A) + w * (16 * 68);
    int r = lane >> 1, half = lane & 1;
    int mg = m0 + w * 16 + r;

    #pragma unroll
    for (int j = 0; j < 4; j++)
        wmma::store_matrix_sync(scr + j * 16, accN[j], 68, wmma::mem_row_major);
    __syncwarp();
    float nv[32];
    {
        const float* srow = scr + r * 68 + half * 32;
        #pragma unroll
        for (int c = 0; c < 32; c++)
            nv[c] = fmaxf(srow[c] + biasN[half * 32 + c], 0.f);
    }
    bool do_sc = (STAGE == 2) ? (mg < M) : (mg == 0);
    if (do_sc) {
        const float* gp = (STAGE == 2)
            ? &gtv[((size_t)b * M + mg) * CH + c0 + half * 32]
            : &gtv[b * CH + c0 + half * 32];
        float sc = 0.f;
        #pragma unroll
        for (int c = 0; c < 32; c++) { float d = gp[c] - nv[c]; sc += d * d; }
        if (STAGE == 2) atomicAdd(&g_sc2[(size_t)b * M2 + mg], sc);
        else            atomicAdd(&g_sc1[b], sc);
    }
    __syncwarp();
    #pragma unroll
    for (int j = 0; j < 4; j++)
        wmma::store_matrix_sync(scr + j * 16, accS[j], 68, wmma::mem_row_major);
    __syncwarp();
    if (mg < M) {
        const float* srow = scr + r * 68 + half * 32;
        float* op = out + ((size_t)b * M + mg) * CH + c0 + half * 32;
        #pragma unroll
        for (int c4 = 0; c4 < 8; c4++) {
            float4 o4;
            o4.x = nv[c4 * 4 + 0] + fmaxf(srow[c4 * 4 + 0] + biasS[half * 32 + c4 * 4 + 0], 0.f);
            o4.y = nv[c4 * 4 + 1] + fmaxf(srow[c4 * 4 + 1] + biasS[half * 32 + c4 * 4 + 1], 0.f);
            o4.z = nv[c4 * 4 + 2] + fmaxf(srow[c4 * 4 + 2] + biasS[half * 32 + c4 * 4 + 2], 0.f);
            o4.w = nv[c4 * 4 + 3] + fmaxf(srow[c4 * 4 + 3] + biasS[half * 32 + c4 * 4 + 3], 0.f);
            *(float4*)(op + c4 * 4) = o4;
        }
    }
}

extern "C" void kernel_launch(void* const* d_in, const int* in_sizes, int n_in,
                              void* d_out, int out_size)
{
    const float* input  = (const float*)d_in[0];
    const float* gt     = (const float*)d_in[1];
    const float* w_att  = (const float*)d_in[2];
    const float* b_att  = (const float*)d_in[3];
    const float* w_gt1  = (const float*)d_in[4];
    const float* b_gt1  = (const float*)d_in[5];
    const float* w_gt2  = (const float*)d_in[6];
    const float* b_gt2  = (const float*)d_in[7];
    const float* w_agg1 = (const float*)d_in[8];
    const float* b_agg1 = (const float*)d_in[9];
    const float* w_src1 = (const float*)d_in[10];
    const float* b_src1 = (const float*)d_in[11];
    const float* w_agg2 = (const float*)d_in[12];
    const float* b_agg2 = (const float*)d_in[13];
    const float* w_src2 = (const float*)d_in[14];
    const float* b_src2 = (const float*)d_in[15];

    float* out    = (float*)d_out;                 // (B*512, 256)
    float* score1 = out + (size_t)NB * M2 * CH;    // (B,)
    float* score2 = score1 + NB;                   // (B*512,)

    cudaFuncSetAttribute(conv_tc_kernel<1>,
                         cudaFuncAttributeMaxDynamicSharedMemorySize, SMEM_TOT);
    cudaFuncSetAttribute(conv_tc_kernel<2>,
                         cudaFuncAttributeMaxDynamicSharedMemorySize, SMEM_TOT);

    // conv1 at captured launch index 3 (for ncu -s/-c), dependencies intact:
    // rowdot -> softmax(+score init) -> gt -> conv1 -> conv2 -> finalize
    rowdot_kernel<<<dim3((LEN1 + 7) / 8, NB), 256>>>(input, w_att);
    attn_softmax_kernel<<<dim3((M1 + 7) / 8, NB), 256>>>(b_att);
    gt_kernel<<<NB * M2 / 16, 256>>>(gt, w_gt1, b_gt1, w_gt2, b_gt2);
    conv_tc_kernel<1><<<dim3((M1 + 127) / 128, NB, 4), 256, SMEM_TOT>>>(
        input, w_agg1, b_agg1, w_src1, b_src1, nullptr);
    conv_tc_kernel<2><<<dim3(M2 / 128, NB, 4), 256, SMEM_TOT>>>(
        input, w_agg2, b_agg2, w_src2, b_src2, out);
    finalize_kernel<<<(NB * M2 + 255) / 256, 256>>>(score1, score2);
}

// round 13
// speedup vs baseline: 1.4570x; 1.0564x over previous
#include <cuda_runtime.h>
#include <cuda_bf16.h>
#include <mma.h>

#define NB   4
#define LEN1 32777
#define M1   4097
#define M2   512
#define CH   256

typedef unsigned long long u64;
typedef unsigned int u32;
using namespace nvcuda;

// ------- static scratch -------
__device__ float g_out1[NB * M1 * CH];
__device__ float g_gt2[NB * M2 * CH];
__device__ float g_gt1_0[NB * CH];
__device__ float g_attn[NB * M1 * 32];
__device__ float g_rowdot[NB * LEN1 * 4];
__device__ float g_sc1[NB];
__device__ float g_sc2[NB * M2];

// ---- f32x2 helpers (gt kernel) ----
__device__ __forceinline__ u64 pk2(float v) {
    u64 r; u32 u = __float_as_uint(v);
    asm("mov.b64 %0, {%1, %1};" : "=l"(r) : "r"(u));
    return r;
}
__device__ __forceinline__ void unpk2(u64 v, float& lo, float& hi) {
    u32 a, b;
    asm("mov.b64 {%0, %1}, %2;" : "=r"(a), "=r"(b) : "l"(v));
    lo = __uint_as_float(a); hi = __uint_as_float(b);
}
#define FMA2(d, a, b) asm("fma.rn.f32x2 %0, %1, %2, %0;" : "+l"(d) : "l"(a), "l"(b))

// pack two floats to bf16x2: low 16 bits = first arg
__device__ __forceinline__ u32 pkbf(float lo_v, float hi_v) {
    u32 r;
    asm("cvt.rn.bf16x2.f32 %0, %1, %2;" : "=r"(r) : "f"(hi_v), "f"(lo_v));
    return r;
}

__device__ __forceinline__ void split4(char* hi, char* lo, int boff,
                                       float v0, float v1, float v2, float v3) {
    u32 h01 = pkbf(v0, v1), h23 = pkbf(v2, v3);
    float r0 = v0 - __uint_as_float(h01 << 16);
    float r1 = v1 - __uint_as_float(h01 & 0xffff0000u);
    float r2 = v2 - __uint_as_float(h23 << 16);
    float r3 = v3 - __uint_as_float(h23 & 0xffff0000u);
    *(uint2*)(hi + boff) = make_uint2(h01, h23);
    *(uint2*)(lo + boff) = make_uint2(pkbf(r0, r1), pkbf(r2, r3));
}
__device__ __forceinline__ void split1(char* hi, char* lo, int boff, float v) {
    u32 h = pkbf(v, 0.f);
    float r = v - __uint_as_float(h << 16);
    u32 l = pkbf(r, 0.f);
    *(unsigned short*)(hi + boff) = (unsigned short)(h & 0xffff);
    *(unsigned short*)(lo + boff) = (unsigned short)(l & 0xffff);
}

// --------------------------------------------------------- finalize
__global__ void finalize_kernel(float* score1, float* score2) {
    int i = blockIdx.x * 256 + threadIdx.x;
    if (i < NB) score1[i] = 1.f - expf(-0.5f * g_sc1[i]);
    if (i < NB * M2) score2[i] = 1.f - expf(-0.5f * g_sc2[i]);
}

// ------------------------------------------------ gt MLP (f32x2, row pairs)
__global__ void __launch_bounds__(256) gt_kernel(
    const float* __restrict__ gt,
    const float* __restrict__ w1, const float* __restrict__ b1,
    const float* __restrict__ w2, const float* __restrict__ b2)
{
    __shared__ float rsT[256][20];
    __shared__ float g1T[256][20];
    int tid = threadIdx.x, r0 = blockIdx.x * 16;

    #pragma unroll
    for (int i = 0; i < 16; i++)
        rsT[tid][i] = gt[(size_t)(r0 + i) * CH + tid];
    __syncthreads();

    u64 acc[8];
    {
        u64 bb = pk2(b1[tid]);
        #pragma unroll
        for (int j = 0; j < 8; j++) acc[j] = bb;
        for (int c = 0; c < CH; c++) {
            u64 w = pk2(w1[c * CH + tid]);
            const ulonglong2* rp = (const ulonglong2*)&rsT[c][0];
            #pragma unroll
            for (int q = 0; q < 4; q++) {
                ulonglong2 a2 = rp[q];
                FMA2(acc[2 * q + 0], a2.x, w);
                FMA2(acc[2 * q + 1], a2.y, w);
            }
        }
    }
    #pragma unroll
    for (int j = 0; j < 8; j++) {
        float lo, hi; unpk2(acc[j], lo, hi);
        g1T[tid][2 * j]     = fmaxf(lo, 0.f);
        g1T[tid][2 * j + 1] = fmaxf(hi, 0.f);
    }
    if ((r0 & 511) == 0)
        g_gt1_0[(r0 >> 9) * CH + tid] = fmaxf(__uint_as_float((u32)acc[0]), 0.f);
    __syncthreads();

    {
        u64 bb = pk2(b2[tid]);
        #pragma unroll
        for (int j = 0; j < 8; j++) acc[j] = bb;
        for (int c = 0; c < CH; c++) {
            u64 w = pk2(w2[c * CH + tid]);
            const ulonglong2* rp = (const ulonglong2*)&g1T[c][0];
            #pragma unroll
            for (int q = 0; q < 4; q++) {
                ulonglong2 a2 = rp[q];
                FMA2(acc[2 * q + 0], a2.x, w);
                FMA2(acc[2 * q + 1], a2.y, w);
            }
        }
    }
    #pragma unroll
    for (int j = 0; j < 8; j++) {
        float lo, hi; unpk2(acc[j], lo, hi);
        g_gt2[(size_t)(r0 + 2 * j)     * CH + tid] = fmaxf(lo, 0.f);
        g_gt2[(size_t)(r0 + 2 * j + 1) * CH + tid] = fmaxf(hi, 0.f);
    }
}

// ------------------------------------- per-row attention dots (streaming)
__global__ void __launch_bounds__(256) rowdot_kernel(
    const float* __restrict__ x, const float* __restrict__ w_att)
{
    __shared__ float wa_s[1024];
    int tid = threadIdx.x;
    *(float4*)&wa_s[tid * 4] = *(const float4*)&w_att[tid * 4];
    __syncthreads();
    int b = blockIdx.y;
    int r = blockIdx.x * 8 + (tid >> 5);
    if (r >= LEN1) return;
    int lane = tid & 31;
    const float* row = x + ((size_t)b * LEN1 + r) * CH;
    float s0 = 0.f, s1 = 0.f, s2 = 0.f, s3 = 0.f;
    #pragma unroll
    for (int j = 0; j < 8; j++) {
        int c = lane + 32 * j;
        float v = row[c];
        float4 w = *(const float4*)&wa_s[c * 4];
        s0 = fmaf(v, w.x, s0); s1 = fmaf(v, w.y, s1);
        s2 = fmaf(v, w.z, s2); s3 = fmaf(v, w.w, s3);
    }
    #pragma unroll
    for (int s = 16; s > 0; s >>= 1) {
        s0 += __shfl_xor_sync(0xffffffff, s0, s);
        s1 += __shfl_xor_sync(0xffffffff, s1, s);
        s2 += __shfl_xor_sync(0xffffffff, s2, s);
        s3 += __shfl_xor_sync(0xffffffff, s3, s);
    }
    if (lane < 4) {
        float v = (lane == 0) ? s0 : (lane == 1) ? s1 : (lane == 2) ? s2 : s3;
        g_rowdot[((size_t)b * LEN1 + r) * 4 + lane] = v;
    }
}

// ------------------------- softmax over 8 nodes + score-accumulator init
__global__ void __launch_bounds__(256) attn_softmax_kernel(const float* __restrict__ b_att)
{
    int tid = threadIdx.x, b = blockIdx.y;
    int m = blockIdx.x * 8 + (tid >> 5);
    if (blockIdx.x == 0 && tid == 0) g_sc1[b] = 0.f;
    int zi = blockIdx.x * 256 + tid;
    if (zi < M2) g_sc2[(size_t)b * M2 + zi] = 0.f;
    if (m >= M1) return;
    int lane = tid & 31;
    int h = lane & 3;
    float lg = g_rowdot[((size_t)b * LEN1 + m) * 4 + h]
             + g_rowdot[((size_t)b * LEN1 + 8 * m + 1) * 4 + lane]
             + b_att[h];
    float mx = lg;
    #pragma unroll
    for (int msk = 4; msk <= 16; msk <<= 1)
        mx = fmaxf(mx, __shfl_xor_sync(0xffffffff, mx, msk));
    float e = expf(lg - mx);
    float sum = e;
    #pragma unroll
    for (int msk = 4; msk <= 16; msk <<= 1)
        sum += __shfl_xor_sync(0xffffffff, sum, msk);
    g_attn[((size_t)b * M1 + m) * 32 + lane] = e / sum;
}

// ---------------- wmma bf16-split fused conv, 2 blocks/SM layout
// src conv runs FIRST; raw accs parked in SRCBUF so accS regs free during node loop.
#define OF_BN   0
#define OF_BS   256
#define OF_ATT  512
#define OF_SRC  4608
#define OF_A    (OF_SRC + 32768)
#define OF_ALO  (OF_A + 18432)
#define OF_B    (OF_A + 36864)
#define OF_BLO  (OF_B + 9216)
#define SMEM_TOT (OF_B + 18432)

template<int STAGE>
__global__ void __launch_bounds__(256, 2) conv_tc_kernel(
    const float* __restrict__ x_in,
    const float* __restrict__ w_node, const float* __restrict__ b_node,
    const float* __restrict__ w_src,  const float* __restrict__ b_src,
    float* __restrict__ outp)
{
    constexpr int M  = (STAGE == 1) ? M1 : M2;
    constexpr int LS = (STAGE == 1) ? LEN1 : M1;
    const float* x   = (STAGE == 1) ? x_in : g_out1;
    const float* gtv = (STAGE == 1) ? g_gt1_0 : g_gt2;
    float*       out = (STAGE == 1) ? g_out1 : outp;

    extern __shared__ char sm[];
    float* biasN = (float*)(sm + OF_BN);
    float* biasS = (float*)(sm + OF_BS);
    float (*attn_s)[8] = (float(*)[8])(sm + OF_ATT);
    float* SRCBUF = (float*)(sm + OF_SRC);           // 128 x 64 raw src accs
    char *AHI = sm + OF_A, *ALO = sm + OF_ALO;
    char *BHI = sm + OF_B, *BLO = sm + OF_BLO;

    int tid = threadIdx.x, w = tid >> 5, lane = tid & 31;
    int b = blockIdx.y, g = blockIdx.z;
    int m0 = blockIdx.x * 128;
    int vrows = M - m0; if (vrows > 128) vrows = 128;
    int c0 = g * 64;

    if (tid < 64) { biasN[tid] = b_node[c0 + tid]; biasS[tid] = b_src[c0 + tid]; }
    for (int i = tid; i < 128 * 8; i += 256) {
        int p = i >> 3, n = i & 7;
        attn_s[p][n] = (p < vrows)
            ? g_attn[((size_t)b * M1 + m0 + p) * 32 + n * 4 + g] : 0.f;
    }

    const float* node_base = x + ((size_t)b * LS + 8 * (size_t)m0 + 1) * CH + c0;
    const float* src_base  = x + ((size_t)b * LS + m0) * CH + c0;

    const __nv_bfloat16* Ah = (const __nv_bfloat16*)AHI;
    const __nv_bfloat16* Al = (const __nv_bfloat16*)ALO;
    const __nv_bfloat16* Bh = (const __nv_bfloat16*)BHI;
    const __nv_bfloat16* Bl = (const __nv_bfloat16*)BLO;

    // ---- src conv FIRST: K=64 ----
    __syncthreads();
    #pragma unroll
    for (int u = 0; u < 8; u++) {
        int idx = (tid >> 2) + u * 64;
        int p = idx >> 2, qg = idx & 3, q = tid & 3;
        int qi = qg * 4 + q;
        bool val = p < vrows;
        float4 v = val ? *(const float4*)(src_base + (size_t)p * CH + qi * 4)
                       : make_float4(0.f, 0.f, 0.f, 0.f);
        split4(AHI, ALO, p * 144 + qi * 8, v.x, v.y, v.z, v.w);
    }
    #pragma unroll
    for (int u = 0; u < 4; u++) {
        int it = tid + u * 256;
        int o = it >> 4, qg = it & 15;
        float4 wv = *(const float4*)(w_src + (size_t)(c0 + o) * 64 + qg * 4);
        split4(BHI, BLO, o * 144 + qg * 8, wv.x, wv.y, wv.z, wv.w);
    }
    __syncthreads();
    {
        wmma::fragment<wmma::accumulator, 16, 16, 16, float> accS[4];
        #pragma unroll
        for (int j = 0; j < 4; j++) wmma::fill_fragment(accS[j], 0.f);
        #pragma unroll
        for (int ks = 0; ks < 4; ks++) {
            wmma::fragment<wmma::matrix_a, 16, 16, 16, __nv_bfloat16, wmma::row_major> ah, al;
            wmma::load_matrix_sync(ah, Ah + (w * 16) * 72 + ks * 16, 72);
            wmma::load_matrix_sync(al, Al + (w * 16) * 72 + ks * 16, 72);
            #pragma unroll
            for (int j = 0; j < 4; j++) {
                wmma::fragment<wmma::matrix_b, 16, 16, 16, __nv_bfloat16, wmma::col_major> bh, bl;
                wmma::load_matrix_sync(bh, Bh + (j * 16) * 72 + ks * 16, 72);
                wmma::load_matrix_sync(bl, Bl + (j * 16) * 72 + ks * 16, 72);
                wmma::mma_sync(accS[j], ah, bh, accS[j]);
                wmma::mma_sync(accS[j], ah, bl, accS[j]);
                wmma::mma_sync(accS[j], al, bh, accS[j]);
            }
        }
        #pragma unroll
        for (int j = 0; j < 4; j++)
            wmma::store_matrix_sync(SRCBUF + (w * 16) * 64 + j * 16, accS[j], 64,
                                    wmma::mem_row_major);
    }

    // ---- node conv: K=256, 4 chunks of 64 ----
    wmma::fragment<wmma::accumulator, 16, 16, 16, float> accN[4];
    #pragma unroll
    for (int j = 0; j < 4; j++) wmma::fill_fragment(accN[j], 0.f);

    for (int kc = 0; kc < 4; kc++) {
        __syncthreads();
        #pragma unroll
        for (int u = 0; u < 8; u++) {
            int idx = (tid >> 2) + u * 64;
            int p = idx >> 2, t = idx & 3, q = tid & 3;
            bool val = p < vrows;
            float a0 = val ? attn_s[p][2 * t]     : 0.f;
            float a1 = val ? attn_s[p][2 * t + 1] : 0.f;
            const float* r0 = node_base + (size_t)(8 * p + 2 * t) * CH + kc * 16 + q * 4;
            float4 v0 = val ? *(const float4*)r0        : make_float4(0.f, 0.f, 0.f, 0.f);
            float4 v1 = val ? *(const float4*)(r0 + CH) : make_float4(0.f, 0.f, 0.f, 0.f);
            split4(AHI, ALO, p * 144 + (t * 16 + q * 4) * 2,
                   fmaf(a0, v0.x, a1 * v1.x), fmaf(a0, v0.y, a1 * v1.y),
                   fmaf(a0, v0.z, a1 * v1.z), fmaf(a0, v0.w, a1 * v1.w));
        }
        #pragma unroll
        for (int u = 0; u < 4; u++) {
            int it = tid + u * 256;
            int o = it >> 4, cl = it & 15;
            float4 wv = *(const float4*)(w_node + (size_t)(c0 + o) * 256 + (kc * 16 + cl) * 4);
            split1(BHI, BLO, o * 144 + (0 * 16 + cl) * 2, wv.x);
            split1(BHI, BLO, o * 144 + (1 * 16 + cl) * 2, wv.y);
            split1(BHI, BLO, o * 144 + (2 * 16 + cl) * 2, wv.z);
            split1(BHI, BLO, o * 144 + (3 * 16 + cl) * 2, wv.w);
        }
        __syncthreads();
        #pragma unroll
        for (int ks = 0; ks < 4; ks++) {
            wmma::fragment<wmma::matrix_a, 16, 16, 16, __nv_bfloat16, wmma::row_major> ah, al;
            wmma::load_matrix_sync(ah, Ah + (w * 16) * 72 + ks * 16, 72);
            wmma::load_matrix_sync(al, Al + (w * 16) * 72 + ks * 16, 72);
            #pragma unroll
            for (int j = 0; j < 4; j++) {
                wmma::fragment<wmma::matrix_b, 16, 16, 16, __nv_bfloat16, wmma::col_major> bh, bl;
                wmma::load_matrix_sync(bh, Bh + (j * 16) * 72 + ks * 16, 72);
                wmma::load_matrix_sync(bl, Bl + (j * 16) * 72 + ks * 16, 72);
                wmma::mma_sync(accN[j], ah, bh, accN[j]);
                wmma::mma_sync(accN[j], ah, bl, accN[j]);
                wmma::mma_sync(accN[j], al, bh, accN[j]);
            }
        }
    }
    __syncthreads();

    // ---- epilogue: accN via per-warp scratch (A region), src from SRCBUF ----
    float* scr = (float*)(sm + OF_A) + w * (16 * 68);
    int r = lane >> 1, half = lane & 1;
    int mg = m0 + w * 16 + r;

    #pragma unroll
    for (int j = 0; j < 4; j++)
        wmma::store_matrix_sync(scr + j * 16, accN[j], 68, wmma::mem_row_major);
    __syncwarp();

    float nv[32];
    {
        const float* srow = scr + r * 68 + half * 32;
        #pragma unroll
        for (int c = 0; c < 32; c++)
            nv[c] = fmaxf(srow[c] + biasN[half * 32 + c], 0.f);
    }
    bool do_sc = (STAGE == 2) ? (mg < M) : (mg == 0);
    if (do_sc) {
        const float* gp = (STAGE == 2)
            ? &gtv[((size_t)b * M + mg) * CH + c0 + half * 32]
            : &gtv[b * CH + c0 + half * 32];
        float sc = 0.f;
        #pragma unroll
        for (int c = 0; c < 32; c++) { float d = gp[c] - nv[c]; sc += d * d; }
        if (STAGE == 2) atomicAdd(&g_sc2[(size_t)b * M2 + mg], sc);
        else            atomicAdd(&g_sc1[b], sc);
    }
    if (mg < M) {
        const float* srow = SRCBUF + (w * 16 + r) * 64 + half * 32;
        float* op = out + ((size_t)b * M + mg) * CH + c0 + half * 32;
        #pragma unroll
        for (int c4 = 0; c4 < 8; c4++) {
            float4 o4;
            o4.x = nv[c4 * 4 + 0] + fmaxf(srow[c4 * 4 + 0] + biasS[half * 32 + c4 * 4 + 0], 0.f);
            o4.y = nv[c4 * 4 + 1] + fmaxf(srow[c4 * 4 + 1] + biasS[half * 32 + c4 * 4 + 1], 0.f);
            o4.z = nv[c4 * 4 + 2] + fmaxf(srow[c4 * 4 + 2] + biasS[half * 32 + c4 * 4 + 2], 0.f);
            o4.w = nv[c4 * 4 + 3] + fmaxf(srow[c4 * 4 + 3] + biasS[half * 32 + c4 * 4 + 3], 0.f);
            *(float4*)(op + c4 * 4) = o4;
        }
    }
}

extern "C" void kernel_launch(void* const* d_in, const int* in_sizes, int n_in,
                              void* d_out, int out_size)
{
    const float* input  = (const float*)d_in[0];
    const float* gt     = (const float*)d_in[1];
    const float* w_att  = (const float*)d_in[2];
    const float* b_att  = (const float*)d_in[3];
    const float* w_gt1  = (const float*)d_in[4];
    const float* b_gt1  = (const float*)d_in[5];
    const float* w_gt2  = (const float*)d_in[6];
    const float* b_gt2  = (const float*)d_in[7];
    const float* w_agg1 = (const float*)d_in[8];
    const float* b_agg1 = (const float*)d_in[9];
    const float* w_src1 = (const float*)d_in[10];
    const float* b_src1 = (const float*)d_in[11];
    const float* w_agg2 = (const float*)d_in[12];
    const float* b_agg2 = (const float*)d_in[13];
    const float* w_src2 = (const float*)d_in[14];
    const float* b_src2 = (const float*)d_in[15];

    float* out    = (float*)d_out;                 // (B*512, 256)
    float* score1 = out + (size_t)NB * M2 * CH;    // (B,)
    float* score2 = score1 + NB;                   // (B*512,)

    cudaFuncSetAttribute(conv_tc_kernel<1>,
                         cudaFuncAttributeMaxDynamicSharedMemorySize, SMEM_TOT);
    cudaFuncSetAttribute(conv_tc_kernel<2>,
                         cudaFuncAttributeMaxDynamicSharedMemorySize, SMEM_TOT);

    // conv1 at captured launch index 3 (for ncu -s/-c), dependencies intact:
    // rowdot -> softmax(+score init) -> gt -> conv1 -> conv2 -> finalize
    rowdot_kernel<<<dim3((LEN1 + 7) / 8, NB), 256>>>(input, w_att);
    attn_softmax_kernel<<<dim3((M1 + 7) / 8, NB), 256>>>(b_att);
    gt_kernel<<<NB * M2 / 16, 256>>>(gt, w_gt1, b_gt1, w_gt2, b_gt2);
    conv_tc_kernel<1><<<dim3((M1 + 127) / 128, NB, 4), 256, SMEM_TOT>>>(
        input, w_agg1, b_agg1, w_src1, b_src1, nullptr);
    conv_tc_kernel<2><<<dim3(M2 / 128, NB, 4), 256, SMEM_TOT>>>(
        input, w_agg2, b_agg2, w_src2, b_src2, out);
    finalize_kernel<<<(NB * M2 + 255) / 256, 256>>>(score1, score2);
}

// round 14
// speedup vs baseline: 1.5830x; 1.0865x over previous
#include <cuda_runtime.h>
#include <cuda_bf16.h>
#include <mma.h>

#define NB   4
#define LEN1 32777
#define M1   4097
#define M2   512
#define CH   256

typedef unsigned long long u64;
typedef unsigned int u32;
using namespace nvcuda;

// ------- static scratch -------
__device__ float g_out1[NB * M1 * CH];
__device__ float g_gt2[NB * M2 * CH];
__device__ float g_gt1_0[NB * CH];
__device__ float g_attn[NB * M1 * 32];
__device__ float g_rowdot[NB * LEN1 * 4];
__device__ float g_sc1[NB];
__device__ float g_sc2[NB * M2];

// ---- f32x2 helpers (gt kernel) ----
__device__ __forceinline__ u64 pk2(float v) {
    u64 r; u32 u = __float_as_uint(v);
    asm("mov.b64 %0, {%1, %1};" : "=l"(r) : "r"(u));
    return r;
}
__device__ __forceinline__ void unpk2(u64 v, float& lo, float& hi) {
    u32 a, b;
    asm("mov.b64 {%0, %1}, %2;" : "=r"(a), "=r"(b) : "l"(v));
    lo = __uint_as_float(a); hi = __uint_as_float(b);
}
#define FMA2(d, a, b) asm("fma.rn.f32x2 %0, %1, %2, %0;" : "+l"(d) : "l"(a), "l"(b))

// pack two floats to bf16x2: low 16 bits = first arg
__device__ __forceinline__ u32 pkbf(float lo_v, float hi_v) {
    u32 r;
    asm("cvt.rn.bf16x2.f32 %0, %1, %2;" : "=r"(r) : "f"(hi_v), "f"(lo_v));
    return r;
}

__device__ __forceinline__ void split4(char* hi, char* lo, int boff,
                                       float v0, float v1, float v2, float v3) {
    u32 h01 = pkbf(v0, v1), h23 = pkbf(v2, v3);
    float r0 = v0 - __uint_as_float(h01 << 16);
    float r1 = v1 - __uint_as_float(h01 & 0xffff0000u);
    float r2 = v2 - __uint_as_float(h23 << 16);
    float r3 = v3 - __uint_as_float(h23 & 0xffff0000u);
    *(uint2*)(hi + boff) = make_uint2(h01, h23);
    *(uint2*)(lo + boff) = make_uint2(pkbf(r0, r1), pkbf(r2, r3));
}
__device__ __forceinline__ void split1(char* hi, char* lo, int boff, float v) {
    u32 h = pkbf(v, 0.f);
    float r = v - __uint_as_float(h << 16);
    u32 l = pkbf(r, 0.f);
    *(unsigned short*)(hi + boff) = (unsigned short)(h & 0xffff);
    *(unsigned short*)(lo + boff) = (unsigned short)(l & 0xffff);
}

// --------------------------------------------------------- finalize
__global__ void finalize_kernel(float* score1, float* score2) {
    int i = blockIdx.x * 256 + threadIdx.x;
    if (i < NB) score1[i] = 1.f - expf(-0.5f * g_sc1[i]);
    if (i < NB * M2) score2[i] = 1.f - expf(-0.5f * g_sc2[i]);
}

// ------------------------------------------------ gt MLP (f32x2, row pairs)
__global__ void __launch_bounds__(256) gt_kernel(
    const float* __restrict__ gt,
    const float* __restrict__ w1, const float* __restrict__ b1,
    const float* __restrict__ w2, const float* __restrict__ b2)
{
    __shared__ float rsT[256][20];
    __shared__ float g1T[256][20];
    int tid = threadIdx.x, r0 = blockIdx.x * 16;

    #pragma unroll
    for (int i = 0; i < 16; i++)
        rsT[tid][i] = gt[(size_t)(r0 + i) * CH + tid];
    __syncthreads();

    u64 acc[8];
    {
        u64 bb = pk2(b1[tid]);
        #pragma unroll
        for (int j = 0; j < 8; j++) acc[j] = bb;
        for (int c = 0; c < CH; c++) {
            u64 w = pk2(w1[c * CH + tid]);
            const ulonglong2* rp = (const ulonglong2*)&rsT[c][0];
            #pragma unroll
            for (int q = 0; q < 4; q++) {
                ulonglong2 a2 = rp[q];
                FMA2(acc[2 * q + 0], a2.x, w);
                FMA2(acc[2 * q + 1], a2.y, w);
            }
        }
    }
    #pragma unroll
    for (int j = 0; j < 8; j++) {
        float lo, hi; unpk2(acc[j], lo, hi);
        g1T[tid][2 * j]     = fmaxf(lo, 0.f);
        g1T[tid][2 * j + 1] = fmaxf(hi, 0.f);
    }
    if ((r0 & 511) == 0)
        g_gt1_0[(r0 >> 9) * CH + tid] = fmaxf(__uint_as_float((u32)acc[0]), 0.f);
    __syncthreads();

    {
        u64 bb = pk2(b2[tid]);
        #pragma unroll
        for (int j = 0; j < 8; j++) acc[j] = bb;
        for (int c = 0; c < CH; c++) {
            u64 w = pk2(w2[c * CH + tid]);
            const ulonglong2* rp = (const ulonglong2*)&g1T[c][0];
            #pragma unroll
            for (int q = 0; q < 4; q++) {
                ulonglong2 a2 = rp[q];
                FMA2(acc[2 * q + 0], a2.x, w);
                FMA2(acc[2 * q + 1], a2.y, w);
            }
        }
    }
    #pragma unroll
    for (int j = 0; j < 8; j++) {
        float lo, hi; unpk2(acc[j], lo, hi);
        g_gt2[(size_t)(r0 + 2 * j)     * CH + tid] = fmaxf(lo, 0.f);
        g_gt2[(size_t)(r0 + 2 * j + 1) * CH + tid] = fmaxf(hi, 0.f);
    }
}

// ------------------------------------- per-row attention dots (streaming)
__global__ void __launch_bounds__(256) rowdot_kernel(
    const float* __restrict__ x, const float* __restrict__ w_att)
{
    __shared__ float wa_s[1024];
    int tid = threadIdx.x;
    *(float4*)&wa_s[tid * 4] = *(const float4*)&w_att[tid * 4];
    __syncthreads();
    int b = blockIdx.y;
    int r = blockIdx.x * 8 + (tid >> 5);
    if (r >= LEN1) return;
    int lane = tid & 31;
    const float* row = x + ((size_t)b * LEN1 + r) * CH;
    float s0 = 0.f, s1 = 0.f, s2 = 0.f, s3 = 0.f;
    #pragma unroll
    for (int j = 0; j < 8; j++) {
        int c = lane + 32 * j;
        float v = row[c];
        float4 w = *(const float4*)&wa_s[c * 4];
        s0 = fmaf(v, w.x, s0); s1 = fmaf(v, w.y, s1);
        s2 = fmaf(v, w.z, s2); s3 = fmaf(v, w.w, s3);
    }
    #pragma unroll
    for (int s = 16; s > 0; s >>= 1) {
        s0 += __shfl_xor_sync(0xffffffff, s0, s);
        s1 += __shfl_xor_sync(0xffffffff, s1, s);
        s2 += __shfl_xor_sync(0xffffffff, s2, s);
        s3 += __shfl_xor_sync(0xffffffff, s3, s);
    }
    if (lane < 4) {
        float v = (lane == 0) ? s0 : (lane == 1) ? s1 : (lane == 2) ? s2 : s3;
        g_rowdot[((size_t)b * LEN1 + r) * 4 + lane] = v;
    }
}

// ------------------------- softmax over 8 nodes + score-accumulator init
__global__ void __launch_bounds__(256) attn_softmax_kernel(const float* __restrict__ b_att)
{
    int tid = threadIdx.x, b = blockIdx.y;
    int m = blockIdx.x * 8 + (tid >> 5);
    if (blockIdx.x == 0 && tid == 0) g_sc1[b] = 0.f;
    int zi = blockIdx.x * 256 + tid;
    if (zi < M2) g_sc2[(size_t)b * M2 + zi] = 0.f;
    if (m >= M1) return;
    int lane = tid & 31;
    int h = lane & 3;
    float lg = g_rowdot[((size_t)b * LEN1 + m) * 4 + h]
             + g_rowdot[((size_t)b * LEN1 + 8 * m + 1) * 4 + lane]
             + b_att[h];
    float mx = lg;
    #pragma unroll
    for (int msk = 4; msk <= 16; msk <<= 1)
        mx = fmaxf(mx, __shfl_xor_sync(0xffffffff, mx, msk));
    float e = expf(lg - mx);
    float sum = e;
    #pragma unroll
    for (int msk = 4; msk <= 16; msk <<= 1)
        sum += __shfl_xor_sync(0xffffffff, sum, msk);
    g_attn[((size_t)b * M1 + m) * 32 + lane] = e / sum;
}

// ---------------- wmma bf16-split fused conv, P=64 tile, 3 blocks/SM
// warp w: rows (w&3)*16, output cols (w>>2)*32. src conv first -> SRCBUF.
#define OF_BN   0
#define OF_BS   256
#define OF_ATT  512
#define OF_SRC  2560
#define OF_A    18944
#define OF_ALO  (OF_A + 9216)
#define OF_B    (OF_A + 18432)
#define OF_BLO  (OF_B + 9216)
#define SMEM_TOT (OF_B + 18432)

template<int STAGE>
__global__ void __launch_bounds__(256, 3) conv_tc_kernel(
    const float* __restrict__ x_in,
    const float* __restrict__ w_node, const float* __restrict__ b_node,
    const float* __restrict__ w_src,  const float* __restrict__ b_src,
    float* __restrict__ outp)
{
    constexpr int M  = (STAGE == 1) ? M1 : M2;
    constexpr int LS = (STAGE == 1) ? LEN1 : M1;
    const float* x   = (STAGE == 1) ? x_in : g_out1;
    const float* gtv = (STAGE == 1) ? g_gt1_0 : g_gt2;
    float*       out = (STAGE == 1) ? g_out1 : outp;

    extern __shared__ char sm[];
    float* biasN = (float*)(sm + OF_BN);
    float* biasS = (float*)(sm + OF_BS);
    float (*attn_s)[8] = (float(*)[8])(sm + OF_ATT);
    float* SRCBUF = (float*)(sm + OF_SRC);           // 64 x 64 raw src accs
    char *AHI = sm + OF_A, *ALO = sm + OF_ALO;
    char *BHI = sm + OF_B, *BLO = sm + OF_BLO;

    int tid = threadIdx.x, w = tid >> 5, lane = tid & 31;
    int w4 = w & 3, jp = w >> 2;                     // row group / col pair
    int b = blockIdx.y, g = blockIdx.z;
    int m0 = blockIdx.x * 64;
    int vrows = M - m0; if (vrows > 64) vrows = 64;
    int c0 = g * 64;

    if (tid < 64) { biasN[tid] = b_node[c0 + tid]; biasS[tid] = b_src[c0 + tid]; }
    for (int i = tid; i < 64 * 8; i += 256) {
        int p = i >> 3, n = i & 7;
        attn_s[p][n] = (p < vrows)
            ? g_attn[((size_t)b * M1 + m0 + p) * 32 + n * 4 + g] : 0.f;
    }

    const float* node_base = x + ((size_t)b * LS + 8 * (size_t)m0 + 1) * CH + c0;
    const float* src_base  = x + ((size_t)b * LS + m0) * CH + c0;

    const __nv_bfloat16* Ah = (const __nv_bfloat16*)AHI;
    const __nv_bfloat16* Al = (const __nv_bfloat16*)ALO;
    const __nv_bfloat16* Bh = (const __nv_bfloat16*)BHI;
    const __nv_bfloat16* Bl = (const __nv_bfloat16*)BLO;

    // ---- src conv FIRST: K=64 ----
    __syncthreads();
    #pragma unroll
    for (int u = 0; u < 4; u++) {
        int it = tid + u * 256;
        int p = it >> 4, qi = it & 15;
        bool val = p < vrows;
        float4 v = val ? *(const float4*)(src_base + (size_t)p * CH + qi * 4)
                       : make_float4(0.f, 0.f, 0.f, 0.f);
        split4(AHI, ALO, p * 144 + qi * 8, v.x, v.y, v.z, v.w);
    }
    #pragma unroll
    for (int u = 0; u < 4; u++) {
        int it = tid + u * 256;
        int o = it >> 4, qg = it & 15;
        float4 wv = *(const float4*)(w_src + (size_t)(c0 + o) * 64 + qg * 4);
        split4(BHI, BLO, o * 144 + qg * 8, wv.x, wv.y, wv.z, wv.w);
    }
    __syncthreads();
    {
        wmma::fragment<wmma::accumulator, 16, 16, 16, float> accS[2];
        #pragma unroll
        for (int j = 0; j < 2; j++) wmma::fill_fragment(accS[j], 0.f);
        #pragma unroll
        for (int ks = 0; ks < 4; ks++) {
            wmma::fragment<wmma::matrix_a, 16, 16, 16, __nv_bfloat16, wmma::row_major> ah, al;
            wmma::load_matrix_sync(ah, Ah + (w4 * 16) * 72 + ks * 16, 72);
            wmma::load_matrix_sync(al, Al + (w4 * 16) * 72 + ks * 16, 72);
            #pragma unroll
            for (int j = 0; j < 2; j++) {
                int jc = jp * 2 + j;
                wmma::fragment<wmma::matrix_b, 16, 16, 16, __nv_bfloat16, wmma::col_major> bh, bl;
                wmma::load_matrix_sync(bh, Bh + (jc * 16) * 72 + ks * 16, 72);
                wmma::load_matrix_sync(bl, Bl + (jc * 16) * 72 + ks * 16, 72);
                wmma::mma_sync(accS[j], ah, bh, accS[j]);
                wmma::mma_sync(accS[j], ah, bl, accS[j]);
                wmma::mma_sync(accS[j], al, bh, accS[j]);
            }
        }
        #pragma unroll
        for (int j = 0; j < 2; j++)
            wmma::store_matrix_sync(SRCBUF + (w4 * 16) * 64 + (jp * 2 + j) * 16, accS[j],
                                    64, wmma::mem_row_major);
    }

    // ---- node conv: K=256, 4 chunks of 64 ----
    wmma::fragment<wmma::accumulator, 16, 16, 16, float> accN[2];
    #pragma unroll
    for (int j = 0; j < 2; j++) wmma::fill_fragment(accN[j], 0.f);

    for (int kc = 0; kc < 4; kc++) {
        __syncthreads();
        #pragma unroll
        for (int u = 0; u < 4; u++) {
            int it = tid + u * 256;
            int q = it & 3, rest = it >> 2;
            int p = rest >> 2, t = rest & 3;
            bool val = p < vrows;
            float a0 = val ? attn_s[p][2 * t]     : 0.f;
            float a1 = val ? attn_s[p][2 * t + 1] : 0.f;
            const float* r0 = node_base + (size_t)(8 * p + 2 * t) * CH + kc * 16 + q * 4;
            float4 v0 = val ? *(const float4*)r0        : make_float4(0.f, 0.f, 0.f, 0.f);
            float4 v1 = val ? *(const float4*)(r0 + CH) : make_float4(0.f, 0.f, 0.f, 0.f);
            split4(AHI, ALO, p * 144 + (t * 16 + q * 4) * 2,
                   fmaf(a0, v0.x, a1 * v1.x), fmaf(a0, v0.y, a1 * v1.y),
                   fmaf(a0, v0.z, a1 * v1.z), fmaf(a0, v0.w, a1 * v1.w));
        }
        #pragma unroll
        for (int u = 0; u < 4; u++) {
            int it = tid + u * 256;
            int o = it >> 4, cl = it & 15;
            float4 wv = *(const float4*)(w_node + (size_t)(c0 + o) * 256 + (kc * 16 + cl) * 4);
            split1(BHI, BLO, o * 144 + (0 * 16 + cl) * 2, wv.x);
            split1(BHI, BLO, o * 144 + (1 * 16 + cl) * 2, wv.y);
            split1(BHI, BLO, o * 144 + (2 * 16 + cl) * 2, wv.z);
            split1(BHI, BLO, o * 144 + (3 * 16 + cl) * 2, wv.w);
        }
        __syncthreads();
        #pragma unroll
        for (int ks = 0; ks < 4; ks++) {
            wmma::fragment<wmma::matrix_a, 16, 16, 16, __nv_bfloat16, wmma::row_major> ah, al;
            wmma::load_matrix_sync(ah, Ah + (w4 * 16) * 72 + ks * 16, 72);
            wmma::load_matrix_sync(al, Al + (w4 * 16) * 72 + ks * 16, 72);
            #pragma unroll
            for (int j = 0; j < 2; j++) {
                int jc = jp * 2 + j;
                wmma::fragment<wmma::matrix_b, 16, 16, 16, __nv_bfloat16, wmma::col_major> bh, bl;
                wmma::load_matrix_sync(bh, Bh + (jc * 16) * 72 + ks * 16, 72);
                wmma::load_matrix_sync(bl, Bl + (jc * 16) * 72 + ks * 16, 72);
                wmma::mma_sync(accN[j], ah, bh, accN[j]);
                wmma::mma_sync(accN[j], ah, bl, accN[j]);
                wmma::mma_sync(accN[j], al, bh, accN[j]);
            }
        }
    }
    __syncthreads();

    // ---- epilogue: accN via per-warp scratch (A region), src from SRCBUF ----
    float* scr = (float*)(sm + OF_A) + w * (16 * 36);
    #pragma unroll
    for (int j = 0; j < 2; j++)
        wmma::store_matrix_sync(scr + j * 16, accN[j], 36, wmma::mem_row_major);
    __syncwarp();

    int r = lane >> 1, half = lane & 1;
    int mg = m0 + w4 * 16 + r;
    int gc = jp * 32 + half * 16;              // column base within group

    float nv[16];
    {
        const float* srow = scr + r * 36 + half * 16;
        #pragma unroll
        for (int c = 0; c < 16; c++)
            nv[c] = fmaxf(srow[c] + biasN[gc + c], 0.f);
    }
    bool do_sc = (STAGE == 2) ? (mg < M) : (mg == 0);
    if (do_sc) {
        const float* gp = (STAGE == 2)
            ? &gtv[((size_t)b * M + mg) * CH + c0 + gc]
            : &gtv[b * CH + c0 + gc];
        float sc = 0.f;
        #pragma unroll
        for (int c = 0; c < 16; c++) { float d = gp[c] - nv[c]; sc += d * d; }
        if (STAGE == 2) atomicAdd(&g_sc2[(size_t)b * M2 + mg], sc);
        else            atomicAdd(&g_sc1[b], sc);
    }
    if (mg < M) {
        const float* srow = SRCBUF + (w4 * 16 + r) * 64 + gc;
        float* op = out + ((size_t)b * M + mg) * CH + c0 + gc;
        #pragma unroll
        for (int c4 = 0; c4 < 4; c4++) {
            float4 o4;
            o4.x = nv[c4 * 4 + 0] + fmaxf(srow[c4 * 4 + 0] + biasS[gc + c4 * 4 + 0], 0.f);
            o4.y = nv[c4 * 4 + 1] + fmaxf(srow[c4 * 4 + 1] + biasS[gc + c4 * 4 + 1], 0.f);
            o4.z = nv[c4 * 4 + 2] + fmaxf(srow[c4 * 4 + 2] + biasS[gc + c4 * 4 + 2], 0.f);
            o4.w = nv[c4 * 4 + 3] + fmaxf(srow[c4 * 4 + 3] + biasS[gc + c4 * 4 + 3], 0.f);
            *(float4*)(op + c4 * 4) = o4;
        }
    }
}

extern "C" void kernel_launch(void* const* d_in, const int* in_sizes, int n_in,
                              void* d_out, int out_size)
{
    const float* input  = (const float*)d_in[0];
    const float* gt     = (const float*)d_in[1];
    const float* w_att  = (const float*)d_in[2];
    const float* b_att  = (const float*)d_in[3];
    const float* w_gt1  = (const float*)d_in[4];
    const float* b_gt1  = (const float*)d_in[5];
    const float* w_gt2  = (const float*)d_in[6];
    const float* b_gt2  = (const float*)d_in[7];
    const float* w_agg1 = (const float*)d_in[8];
    const float* b_agg1 = (const float*)d_in[9];
    const float* w_src1 = (const float*)d_in[10];
    const float* b_src1 = (const float*)d_in[11];
    const float* w_agg2 = (const float*)d_in[12];
    const float* b_agg2 = (const float*)d_in[13];
    const float* w_src2 = (const float*)d_in[14];
    const float* b_src2 = (const float*)d_in[15];

    float* out    = (float*)d_out;                 // (B*512, 256)
    float* score1 = out + (size_t)NB * M2 * CH;    // (B,)
    float* score2 = score1 + NB;                   // (B*512,)

    cudaFuncSetAttribute(conv_tc_kernel<1>,
                         cudaFuncAttributeMaxDynamicSharedMemorySize, SMEM_TOT);
    cudaFuncSetAttribute(conv_tc_kernel<2>,
                         cudaFuncAttributeMaxDynamicSharedMemorySize, SMEM_TOT);

    // conv1 at captured launch index 3 (for ncu -s/-c), dependencies intact:
    // rowdot -> softmax(+score init) -> gt -> conv1 -> conv2 -> finalize
    rowdot_kernel<<<dim3((LEN1 + 7) / 8, NB), 256>>>(input, w_att);
    attn_softmax_kernel<<<dim3((M1 + 7) / 8, NB), 256>>>(b_att);
    gt_kernel<<<NB * M2 / 16, 256>>>(gt, w_gt1, b_gt1, w_gt2, b_gt2);
    conv_tc_kernel<1><<<dim3((M1 + 63) / 64, NB, 4), 256, SMEM_TOT>>>(
        input, w_agg1, b_agg1, w_src1, b_src1, nullptr);
    conv_tc_kernel<2><<<dim3(M2 / 64, NB, 4), 256, SMEM_TOT>>>(
        input, w_agg2, b_agg2, w_src2, b_src2, out);
    finalize_kernel<<<(NB * M2 + 255) / 256, 256>>>(score1, score2);
}